// round 1
// baseline (speedup 1.0000x reference)
#include <cuda_runtime.h>
#include <cuda_bf16.h>
#include <stdint.h>

// ---------------------------------------------------------------------------
// GraphSAGE (max-agg) fused pipeline, fp32.
// Inputs (metadata order):
//  0: x           [100000,128] f32
//  1: edge_index  [2,1600000]  i32  (row0=src, row1=dst)
//  2: W_in [128,128]  3: b_in[128]
//  4: W_l1  5: b_l1  6: W_r1
//  7: W_l2  8: b_l2  9: W_r2
// 10: W_l3 11: b_l3 12: W_r3
// 13: g1 14: be1 15: g2 16: be2 17: g3 18: be3
// 19: W_fc1 [64,128] 20: b_fc1[64] 21: W_fc2 [1,64] 22: b_fc2[1]
// Output: [100000,1] f32
// ---------------------------------------------------------------------------

#define NMAX 100000
#define EMAX 1600000
#define HID 128
#define RB  256     // batchnorm partial blocks
#define NEG 0.01f

// -------------------- device scratch (no allocation allowed) ---------------
__device__ float g_H0[NMAX * HID];   // input-proj output == residual
__device__ float g_H [NMAX * HID];   // current activations
__device__ float g_A [NMAX * HID];   // max-aggregated neighbors
__device__ float g_Z [NMAX * HID];   // pre-batchnorm GEMM output
__device__ int   g_deg [NMAX];
__device__ int   g_off [NMAX + 1];
__device__ int   g_cur [NMAX];
__device__ int   g_srcs[EMAX];
__device__ float g_part[RB * 2 * HID];
__device__ float g_stats[2 * HID];   // [0:128) scale = g*rstd, [128:256) shift
__device__ int   g_bsum[128];

// -------------------- small helpers ----------------------------------------
__device__ __forceinline__ unsigned long long pack_dup(float a) {
    unsigned long long r;
    asm("mov.b64 %0, {%1, %1};" : "=l"(r) : "f"(a));
    return r;
}
__device__ __forceinline__ void fma2(unsigned long long& d,
                                     unsigned long long a, unsigned long long b) {
    asm("fma.rn.f32x2 %0, %1, %2, %0;" : "+l"(d) : "l"(a), "l"(b));
}
union F2u { unsigned long long u; float2 f; };

// ============================ CSR construction ==============================
__global__ void k_zero_deg(int M) {
    int i = blockIdx.x * blockDim.x + threadIdx.x;
    if (i < M) g_deg[i] = 0;
}

__global__ void k_count(const int* __restrict__ dst, int E) {
    int e = blockIdx.x * blockDim.x + threadIdx.x;
    if (e < E) atomicAdd(&g_deg[dst[e]], 1);
}

__global__ void k_scanA(int M) {
    __shared__ int sh[1024];
    int i = blockIdx.x * 1024 + threadIdx.x;
    int v = (i < M) ? g_deg[i] : 0;
    sh[threadIdx.x] = v;
    __syncthreads();
    #pragma unroll
    for (int d = 1; d < 1024; d <<= 1) {
        int t = (threadIdx.x >= d) ? sh[threadIdx.x - d] : 0;
        __syncthreads();
        sh[threadIdx.x] += t;
        __syncthreads();
    }
    if (i < M) g_off[i + 1] = sh[threadIdx.x];
    if (threadIdx.x == 1023) g_bsum[blockIdx.x] = sh[1023];
}

__global__ void k_scanB(int nb) {
    // single thread: exclusive scan of block sums (nb <= 128)
    int s = 0;
    for (int b = 0; b < nb; b++) { int v = g_bsum[b]; g_bsum[b] = s; s += v; }
}

__global__ void k_scanC(int M) {
    int i = blockIdx.x * blockDim.x + threadIdx.x;
    if (i < M) {
        int inc = g_off[i + 1] + g_bsum[i >> 10];
        g_off[i + 1] = inc;
        g_cur[i] = inc - g_deg[i];
        if (i == 0) g_off[0] = 0;
    }
}

__global__ void k_scatter(const int* __restrict__ src, const int* __restrict__ dst, int E) {
    int e = blockIdx.x * blockDim.x + threadIdx.x;
    if (e < E) {
        int pos = atomicAdd(&g_cur[dst[e]], 1);
        g_srcs[pos] = src[e];
    }
}

// ============================ max aggregation ===============================
// one block (128 threads) per node; thread = feature; CSR neighbor list.
__global__ void k_agg(int hinIsH0, int M) {
    const float* __restrict__ Hin = hinIsH0 ? g_H0 : g_H;
    int n = blockIdx.x;
    if (n >= M) return;
    int t = threadIdx.x;
    int s = g_off[n], e = g_off[n + 1];
    float m = __int_as_float(0xff800000);  // -inf
    int j = s;
    for (; j + 4 <= e; j += 4) {
        int s0 = g_srcs[j], s1 = g_srcs[j + 1], s2 = g_srcs[j + 2], s3 = g_srcs[j + 3];
        float v0 = Hin[s0 * HID + t];
        float v1 = Hin[s1 * HID + t];
        float v2 = Hin[s2 * HID + t];
        float v3 = Hin[s3 * HID + t];
        m = fmaxf(m, fmaxf(fmaxf(v0, v1), fmaxf(v2, v3)));
    }
    for (; j < e; ++j) m = fmaxf(m, Hin[g_srcs[j] * HID + t]);
    g_A[n * HID + t] = (e > s) ? m : 0.0f;
}

// ============================ GEMM (fp32, f32x2 FMA) ========================
// layered==0: g_H0  := Aext @ W0^T + bias                        (input proj)
// layered==1: g_Z   := g_A @ W0^T + Hin @ W1^T + bias            (SAGE layer)
__global__ __launch_bounds__(256) void gemm_sage(
    const float* __restrict__ Aext,
    const float* __restrict__ W0,
    const float* __restrict__ W1,
    const float* __restrict__ bias,
    int M, int layered, int hinIsH0)
{
    __shared__ float As[16][132];
    __shared__ float Ws[16][132];

    int tid = threadIdx.x;
    int tx = tid & 15;      // col block: tx*8
    int ty = tid >> 4;      // row block: ty*8
    int m0 = blockIdx.x * 128;

    int lr = tid >> 2;          // 0..63 (row)
    int lc = (tid & 3) << 2;    // 0,4,8,12 (k col group)

    unsigned long long acc2[8][4];
    #pragma unroll
    for (int i = 0; i < 8; i++)
        #pragma unroll
        for (int j = 0; j < 4; j++) acc2[i][j] = 0ull;

    const float* Amats[2];
    const float* Wmats[2];
    int nm;
    if (layered) {
        Amats[0] = g_A; Wmats[0] = W0;
        Amats[1] = hinIsH0 ? g_H0 : g_H; Wmats[1] = W1;
        nm = 2;
    } else {
        Amats[0] = Aext; Wmats[0] = W0; nm = 1;
    }

    for (int mm = 0; mm < nm; ++mm) {
        const float* __restrict__ A = Amats[mm];
        const float* __restrict__ W = Wmats[mm];
        for (int k0 = 0; k0 < 128; k0 += 16) {
            #pragma unroll
            for (int h = 0; h < 2; ++h) {
                int row = lr + h * 64;
                int gm = m0 + row;
                float4 v = (gm < M) ? *(const float4*)&A[(size_t)gm * HID + k0 + lc]
                                    : make_float4(0.f, 0.f, 0.f, 0.f);
                As[lc + 0][row] = v.x; As[lc + 1][row] = v.y;
                As[lc + 2][row] = v.z; As[lc + 3][row] = v.w;
            }
            #pragma unroll
            for (int h = 0; h < 2; ++h) {
                int n = lr + h * 64;
                float4 v = *(const float4*)&W[n * HID + k0 + lc];
                Ws[lc + 0][n] = v.x; Ws[lc + 1][n] = v.y;
                Ws[lc + 2][n] = v.z; Ws[lc + 3][n] = v.w;
            }
            __syncthreads();
            #pragma unroll
            for (int kk = 0; kk < 16; ++kk) {
                float a[8];
                *(float4*)&a[0] = *(const float4*)&As[kk][ty * 8];
                *(float4*)&a[4] = *(const float4*)&As[kk][ty * 8 + 4];
                longlong2 bb0 = *(const longlong2*)&Ws[kk][tx * 8];
                longlong2 bb1 = *(const longlong2*)&Ws[kk][tx * 8 + 4];
                unsigned long long b2[4] = {
                    (unsigned long long)bb0.x, (unsigned long long)bb0.y,
                    (unsigned long long)bb1.x, (unsigned long long)bb1.y };
                #pragma unroll
                for (int i = 0; i < 8; i++) {
                    unsigned long long av = pack_dup(a[i]);
                    fma2(acc2[i][0], av, b2[0]);
                    fma2(acc2[i][1], av, b2[1]);
                    fma2(acc2[i][2], av, b2[2]);
                    fma2(acc2[i][3], av, b2[3]);
                }
            }
            __syncthreads();
        }
    }

    float* __restrict__ Z = layered ? g_Z : g_H0;
    float bv[8];
    *(float4*)&bv[0] = *(const float4*)&bias[tx * 8];
    *(float4*)&bv[4] = *(const float4*)&bias[tx * 8 + 4];

    #pragma unroll
    for (int i = 0; i < 8; i++) {
        int gm = m0 + ty * 8 + i;
        if (gm < M) {
            F2u u0, u1, u2, u3;
            u0.u = acc2[i][0]; u1.u = acc2[i][1]; u2.u = acc2[i][2]; u3.u = acc2[i][3];
            float4 o0 = make_float4(u0.f.x + bv[0], u0.f.y + bv[1], u1.f.x + bv[2], u1.f.y + bv[3]);
            float4 o1 = make_float4(u2.f.x + bv[4], u2.f.y + bv[5], u3.f.x + bv[6], u3.f.y + bv[7]);
            *(float4*)&Z[(size_t)gm * HID + tx * 8]     = o0;
            *(float4*)&Z[(size_t)gm * HID + tx * 8 + 4] = o1;
        }
    }
}

// ============================ batchnorm =====================================
__global__ void k_bnpart(int M) {
    int t = threadIdx.x;              // 128: column
    int b = blockIdx.x;               // RB blocks
    int chunk = (M + RB - 1) / RB;
    int r0 = b * chunk;
    int r1 = min(M, r0 + chunk);
    float s = 0.f, q = 0.f;
    for (int r = r0; r < r1; r++) {
        float v = g_Z[(size_t)r * HID + t];
        s += v; q += v * v;
    }
    g_part[b * 256 + t] = s;
    g_part[b * 256 + 128 + t] = q;
}

__global__ void k_bnfinal(const float* __restrict__ g, const float* __restrict__ be, int M) {
    int t = threadIdx.x;  // 128
    double s = 0.0, q = 0.0;
    for (int b = 0; b < RB; b++) {
        s += (double)g_part[b * 256 + t];
        q += (double)g_part[b * 256 + 128 + t];
    }
    double mean = s / (double)M;
    double var = q / (double)M - mean * mean;
    float rstd = (float)(1.0 / sqrt(var + 1e-5));
    float scale = g[t] * rstd;
    g_stats[t] = scale;
    g_stats[128 + t] = be[t] - (float)mean * scale;
}

__global__ void k_bnapply(int M) {
    __shared__ float sc[128], sh[128];
    if (threadIdx.x < 128) {
        sc[threadIdx.x] = g_stats[threadIdx.x];
        sh[threadIdx.x] = g_stats[128 + threadIdx.x];
    }
    __syncthreads();
    int total = M * (HID / 4);
    const float4* Z4 = (const float4*)g_Z;
    float4* H4 = (float4*)g_H;
    for (int idx = blockIdx.x * blockDim.x + threadIdx.x; idx < total;
         idx += gridDim.x * blockDim.x) {
        int c = (idx & 31) * 4;
        float4 z = Z4[idx];
        z.x = z.x * sc[c + 0] + sh[c + 0]; z.x = z.x > 0.f ? z.x : NEG * z.x;
        z.y = z.y * sc[c + 1] + sh[c + 1]; z.y = z.y > 0.f ? z.y : NEG * z.y;
        z.z = z.z * sc[c + 2] + sh[c + 2]; z.z = z.z > 0.f ? z.z : NEG * z.z;
        z.w = z.w * sc[c + 3] + sh[c + 3]; z.w = z.w > 0.f ? z.w : NEG * z.w;
        H4[idx] = z;
    }
}

// ============================ head: residual + fc1 + fc2 ====================
__global__ __launch_bounds__(128) void k_fc(
    const float* __restrict__ W1, const float* __restrict__ b1,
    const float* __restrict__ W2, const float* __restrict__ b2,
    float* __restrict__ out, int M)
{
    __shared__ float W1s[64][129];
    __shared__ float ts[128];
    __shared__ float fps[128];
    __shared__ float b1s[64], w2s[64];
    __shared__ float ws[2];

    int tid = threadIdx.x;
    for (int i = tid; i < 64 * 128; i += 128) W1s[i >> 7][i & 127] = W1[i];
    if (tid < 64) { b1s[tid] = b1[tid]; w2s[tid] = W2[tid]; }
    __syncthreads();

    float bias2 = b2[0];
    const int ROWS = 32;
    int r0 = blockIdx.x * ROWS;

    for (int rr = 0; rr < ROWS; rr++) {
        int r = r0 + rr;
        if (r >= M) break;   // uniform
        ts[tid] = g_H[(size_t)r * HID + tid] + g_H0[(size_t)r * HID + tid];
        __syncthreads();
        int j = tid & 63;
        int half = (tid >> 6) * 64;
        float fp = 0.f;
        #pragma unroll 16
        for (int k = 0; k < 64; k++) fp += W1s[j][half + k] * ts[half + k];
        fps[tid] = fp;
        __syncthreads();
        float contrib = 0.f;
        if (tid < 64) {
            float f = fps[tid] + fps[tid + 64] + b1s[tid];
            f = f > 0.f ? f : NEG * f;
            contrib = f * w2s[tid];
        }
        if (tid < 64) {
            #pragma unroll
            for (int o = 16; o > 0; o >>= 1)
                contrib += __shfl_down_sync(0xffffffff, contrib, o);
            if ((tid & 31) == 0) ws[tid >> 5] = contrib;
        }
        __syncthreads();
        if (tid == 0) out[r] = ws[0] + ws[1] + bias2;
        __syncthreads();
    }
}

// ============================ launch ========================================
extern "C" void kernel_launch(void* const* d_in, const int* in_sizes, int n_in,
                              void* d_out, int out_size)
{
    const float* x    = (const float*)d_in[0];
    const int*   ei   = (const int*)d_in[1];
    const float* W_in = (const float*)d_in[2];
    const float* b_in = (const float*)d_in[3];
    const float* Wl[3] = { (const float*)d_in[4], (const float*)d_in[7], (const float*)d_in[10] };
    const float* bl[3] = { (const float*)d_in[5], (const float*)d_in[8], (const float*)d_in[11] };
    const float* Wr[3] = { (const float*)d_in[6], (const float*)d_in[9], (const float*)d_in[12] };
    const float* gm[3] = { (const float*)d_in[13], (const float*)d_in[15], (const float*)d_in[17] };
    const float* be[3] = { (const float*)d_in[14], (const float*)d_in[16], (const float*)d_in[18] };
    const float* W_fc1 = (const float*)d_in[19];
    const float* b_fc1 = (const float*)d_in[20];
    const float* W_fc2 = (const float*)d_in[21];
    const float* b_fc2 = (const float*)d_in[22];
    float* out = (float*)d_out;

    int M = in_sizes[0] / HID;
    int E = in_sizes[1] / 2;
    const int* src = ei;
    const int* dst = ei + E;

    int scanBlocks = (M + 1023) / 1024;

    // ---- CSR build (per replay; deterministic: max-agg is order independent)
    k_zero_deg<<<(M + 1023) / 1024, 1024>>>(M);
    k_count<<<(E + 511) / 512, 512>>>(dst, E);
    k_scanA<<<scanBlocks, 1024>>>(M);
    k_scanB<<<1, 1>>>(scanBlocks);
    k_scanC<<<(M + 255) / 256, 256>>>(M);
    k_scatter<<<(E + 511) / 512, 512>>>(src, dst, E);

    int gemmGrid = (M + 127) / 128;

    // ---- input projection: H0 = x @ W_in^T + b_in
    gemm_sage<<<gemmGrid, 256>>>(x, W_in, nullptr, b_in, M, 0, 0);

    // ---- 3 SAGE layers
    for (int L = 0; L < 3; L++) {
        int hinIsH0 = (L == 0) ? 1 : 0;
        k_agg<<<M, 128>>>(hinIsH0, M);
        gemm_sage<<<gemmGrid, 256>>>(nullptr, Wl[L], Wr[L], bl[L], M, 1, hinIsH0);
        k_bnpart<<<RB, 128>>>(M);
        k_bnfinal<<<1, 128>>>(gm[L], be[L], M);
        k_bnapply<<<2048, 256>>>(M);
    }

    // ---- head: out = lrelu((H + H0) @ Wfc1^T + b1) @ Wfc2^T + b2
    k_fc<<<(M + 31) / 32, 128>>>(W_fc1, b_fc1, W_fc2, b_fc2, out, M);
}

// round 2
// speedup vs baseline: 1.0075x; 1.0075x over previous
#include <cuda_runtime.h>
#include <cuda_bf16.h>
#include <stdint.h>

// GraphSAGE max-agg pipeline, fp32, BN fused into GEMM epilogue + consumers.

#define NMAX 100000
#define EMAX 1600000
#define HID 128
#define NEG 0.01f
#define GBMAX 800   // max gemm blocks (ceil(100000/128)=782)

// -------------------- device scratch ---------------------------------------
__device__ float g_H0[NMAX * HID];        // input-proj output == residual
__device__ float g_A [NMAX * HID];        // max-aggregated neighbors
__device__ float g_Zb[2][NMAX * HID];     // ping-pong pre-BN GEMM outputs
__device__ int   g_deg [NMAX];
__device__ int   g_off [NMAX + 1];
__device__ int   g_cur [NMAX];
__device__ int   g_srcs[EMAX];
__device__ float g_part[GBMAX * 256];     // per-gemm-block col sums / sumsq
__device__ float g_statsBuf[2][256];      // [0:128) scale, [128:256) shift
__device__ int   g_bsum[128];

// -------------------- helpers ----------------------------------------------
__device__ __forceinline__ unsigned long long pack_dup(float a) {
    unsigned long long r;
    asm("mov.b64 %0, {%1, %1};" : "=l"(r) : "f"(a));
    return r;
}
__device__ __forceinline__ void fma2(unsigned long long& d,
                                     unsigned long long a, unsigned long long b) {
    asm("fma.rn.f32x2 %0, %1, %2, %0;" : "+l"(d) : "l"(a), "l"(b));
}
union F2u { unsigned long long u; float2 f; };

__device__ __forceinline__ float lrelu(float x) { return fmaxf(x, NEG * x); }

__device__ __forceinline__ float4 xform4(float4 v, float4 sc, float4 sh) {
    v.x = lrelu(fmaf(v.x, sc.x, sh.x));
    v.y = lrelu(fmaf(v.y, sc.y, sh.y));
    v.z = lrelu(fmaf(v.z, sc.z, sh.z));
    v.w = lrelu(fmaf(v.w, sc.w, sh.w));
    return v;
}
__device__ __forceinline__ float4 max4(float4 a, float4 b) {
    a.x = fmaxf(a.x, b.x); a.y = fmaxf(a.y, b.y);
    a.z = fmaxf(a.z, b.z); a.w = fmaxf(a.w, b.w);
    return a;
}

// ============================ CSR construction ==============================
__global__ void k_count(const int* __restrict__ dst, int E) {
    int e = blockIdx.x * blockDim.x + threadIdx.x;
    if (e < E) atomicAdd(&g_deg[dst[e]], 1);
}

__global__ void k_scanA(int M) {
    __shared__ int sh[1024];
    int i = blockIdx.x * 1024 + threadIdx.x;
    int v = (i < M) ? g_deg[i] : 0;
    sh[threadIdx.x] = v;
    __syncthreads();
    #pragma unroll
    for (int d = 1; d < 1024; d <<= 1) {
        int t = (threadIdx.x >= d) ? sh[threadIdx.x - d] : 0;
        __syncthreads();
        sh[threadIdx.x] += t;
        __syncthreads();
    }
    if (i < M) g_off[i + 1] = sh[threadIdx.x];
    if (threadIdx.x == 1023) g_bsum[blockIdx.x] = sh[1023];
}

__global__ void k_scanB(int nb) {  // exclusive scan of <=128 block sums
    int t = threadIdx.x;
    int orig = (t < nb) ? g_bsum[t] : 0;
    int v = orig;
    #pragma unroll
    for (int o = 1; o < 32; o <<= 1) {
        int u = __shfl_up_sync(0xffffffffu, v, o);
        if ((t & 31) >= o) v += u;
    }
    __shared__ int ws[4];
    if ((t & 31) == 31) ws[t >> 5] = v;
    __syncthreads();
    int add = 0;
    #pragma unroll
    for (int w = 0; w < 4; w++) add += (w < (t >> 5)) ? ws[w] : 0;
    v += add;
    if (t < nb) g_bsum[t] = v - orig;  // exclusive
}

__global__ void k_scanC(int M) {
    int i = blockIdx.x * blockDim.x + threadIdx.x;
    if (i < M) {
        int inc = g_off[i + 1] + g_bsum[i >> 10];
        g_off[i + 1] = inc;
        g_cur[i] = inc - g_deg[i];
        if (i == 0) g_off[0] = 0;
    }
}

__global__ void k_scatter(const int* __restrict__ src, const int* __restrict__ dst, int E) {
    int e = blockIdx.x * blockDim.x + threadIdx.x;
    if (e < E) {
        int pos = atomicAdd(&g_cur[dst[e]], 1);
        g_srcs[pos] = src[e];
    }
}

// ============================ max aggregation ===============================
// warp per node, lane = 4 features (float4). Applies BN+lrelu transform of the
// previous layer on the fly (stats!=null).
__global__ __launch_bounds__(256) void k_agg(const float* __restrict__ Hin,
                                             const float* __restrict__ stats,
                                             int hasStats, int M)
{
    int n = blockIdx.x * 8 + (threadIdx.x >> 5);
    if (n >= M) return;
    int lane = threadIdx.x & 31;

    float4 sc, sh;
    if (hasStats) {
        sc = *(const float4*)&stats[lane * 4];
        sh = *(const float4*)&stats[128 + lane * 4];
    }

    int s = g_off[n], e = g_off[n + 1];
    float4 m = make_float4(-3.4e38f, -3.4e38f, -3.4e38f, -3.4e38f);
    int j = s;
    for (; j + 4 <= e; j += 4) {
        int s0 = g_srcs[j], s1 = g_srcs[j + 1], s2 = g_srcs[j + 2], s3 = g_srcs[j + 3];
        float4 v0 = *(const float4*)&Hin[(size_t)s0 * HID + lane * 4];
        float4 v1 = *(const float4*)&Hin[(size_t)s1 * HID + lane * 4];
        float4 v2 = *(const float4*)&Hin[(size_t)s2 * HID + lane * 4];
        float4 v3 = *(const float4*)&Hin[(size_t)s3 * HID + lane * 4];
        if (hasStats) {
            v0 = xform4(v0, sc, sh); v1 = xform4(v1, sc, sh);
            v2 = xform4(v2, sc, sh); v3 = xform4(v3, sc, sh);
        }
        m = max4(m, max4(max4(v0, v1), max4(v2, v3)));
    }
    for (; j < e; ++j) {
        float4 v = *(const float4*)&Hin[(size_t)g_srcs[j] * HID + lane * 4];
        if (hasStats) v = xform4(v, sc, sh);
        m = max4(m, v);
    }
    if (e == s) m = make_float4(0.f, 0.f, 0.f, 0.f);
    *(float4*)&g_A[(size_t)n * HID + lane * 4] = m;
}

// ============================ GEMM (fp32, f32x2 FMA) ========================
// Zout := A0 @ W0^T (+ xform(A1) @ W1^T) + bias ; optional per-block BN partials.
__global__ __launch_bounds__(256) void gemm_sage(
    const float* __restrict__ A0,
    const float* __restrict__ A1,
    const float* __restrict__ prevStats,
    const float* __restrict__ W0,
    const float* __restrict__ W1,
    const float* __restrict__ bias,
    float* __restrict__ Zout,
    float* __restrict__ part,
    int M, int nm, int hasStats)
{
    __shared__ float As[16][132];
    __shared__ float Ws[16][132];
    __shared__ float scs[128], shs[128];

    int tid = threadIdx.x;
    int tx = tid & 15;      // col block: tx*8
    int ty = tid >> 4;      // row block: ty*8
    int m0 = blockIdx.x * 128;

    int lr = tid >> 2;          // 0..63 (row)
    int lc = (tid & 3) << 2;    // 0,4,8,12 (k col group)

    if (hasStats) {
        if (tid < 128) { scs[tid] = prevStats[tid]; shs[tid] = prevStats[128 + tid]; }
        __syncthreads();
    }

    unsigned long long acc2[8][4];
    #pragma unroll
    for (int i = 0; i < 8; i++)
        #pragma unroll
        for (int j = 0; j < 4; j++) acc2[i][j] = 0ull;

    const float* Amats[2] = { A0, A1 };
    const float* Wmats[2] = { W0, W1 };

    for (int mm = 0; mm < nm; ++mm) {
        const float* __restrict__ A = Amats[mm];
        const float* __restrict__ W = Wmats[mm];
        int doX = (mm == 1) && hasStats;
        for (int k0 = 0; k0 < 128; k0 += 16) {
            #pragma unroll
            for (int h = 0; h < 2; ++h) {
                int row = lr + h * 64;
                int gm = m0 + row;
                float4 v = (gm < M) ? *(const float4*)&A[(size_t)gm * HID + k0 + lc]
                                    : make_float4(0.f, 0.f, 0.f, 0.f);
                if (doX) {
                    v.x = lrelu(fmaf(v.x, scs[k0 + lc + 0], shs[k0 + lc + 0]));
                    v.y = lrelu(fmaf(v.y, scs[k0 + lc + 1], shs[k0 + lc + 1]));
                    v.z = lrelu(fmaf(v.z, scs[k0 + lc + 2], shs[k0 + lc + 2]));
                    v.w = lrelu(fmaf(v.w, scs[k0 + lc + 3], shs[k0 + lc + 3]));
                }
                As[lc + 0][row] = v.x; As[lc + 1][row] = v.y;
                As[lc + 2][row] = v.z; As[lc + 3][row] = v.w;
            }
            #pragma unroll
            for (int h = 0; h < 2; ++h) {
                int n = lr + h * 64;
                float4 v = *(const float4*)&W[n * HID + k0 + lc];
                Ws[lc + 0][n] = v.x; Ws[lc + 1][n] = v.y;
                Ws[lc + 2][n] = v.z; Ws[lc + 3][n] = v.w;
            }
            __syncthreads();
            #pragma unroll
            for (int kk = 0; kk < 16; ++kk) {
                float a[8];
                *(float4*)&a[0] = *(const float4*)&As[kk][ty * 8];
                *(float4*)&a[4] = *(const float4*)&As[kk][ty * 8 + 4];
                longlong2 bb0 = *(const longlong2*)&Ws[kk][tx * 8];
                longlong2 bb1 = *(const longlong2*)&Ws[kk][tx * 8 + 4];
                unsigned long long b2[4] = {
                    (unsigned long long)bb0.x, (unsigned long long)bb0.y,
                    (unsigned long long)bb1.x, (unsigned long long)bb1.y };
                #pragma unroll
                for (int i = 0; i < 8; i++) {
                    unsigned long long av = pack_dup(a[i]);
                    fma2(acc2[i][0], av, b2[0]);
                    fma2(acc2[i][1], av, b2[1]);
                    fma2(acc2[i][2], av, b2[2]);
                    fma2(acc2[i][3], av, b2[3]);
                }
            }
            __syncthreads();
        }
    }

    float bv[8];
    *(float4*)&bv[0] = *(const float4*)&bias[tx * 8];
    *(float4*)&bv[4] = *(const float4*)&bias[tx * 8 + 4];

    float colS[8] = {0,0,0,0,0,0,0,0};
    float colQ[8] = {0,0,0,0,0,0,0,0};

    #pragma unroll
    for (int i = 0; i < 8; i++) {
        int gm = m0 + ty * 8 + i;
        if (gm < M) {
            F2u u0, u1, u2, u3;
            u0.u = acc2[i][0]; u1.u = acc2[i][1]; u2.u = acc2[i][2]; u3.u = acc2[i][3];
            float o[8] = { u0.f.x + bv[0], u0.f.y + bv[1], u1.f.x + bv[2], u1.f.y + bv[3],
                           u2.f.x + bv[4], u2.f.y + bv[5], u3.f.x + bv[6], u3.f.y + bv[7] };
            *(float4*)&Zout[(size_t)gm * HID + tx * 8]     = *(float4*)&o[0];
            *(float4*)&Zout[(size_t)gm * HID + tx * 8 + 4] = *(float4*)&o[4];
            #pragma unroll
            for (int j = 0; j < 8; j++) { colS[j] += o[j]; colQ[j] += o[j] * o[j]; }
        }
    }

    if (part) {
        __syncthreads();   // re-use As/Ws
        #pragma unroll
        for (int j = 0; j < 8; j++) {
            As[ty][tx * 8 + j] = colS[j];
            Ws[ty][tx * 8 + j] = colQ[j];
        }
        __syncthreads();
        if (tid < 128) {
            float s = 0.f, q = 0.f;
            #pragma unroll
            for (int t2 = 0; t2 < 16; t2++) { s += As[t2][tid]; q += Ws[t2][tid]; }
            part[blockIdx.x * 256 + tid] = s;
            part[blockIdx.x * 256 + 128 + tid] = q;
        }
    }
}

// ============================ BN stats finalize =============================
__global__ __launch_bounds__(1024) void k_bnfinal(
    const float* __restrict__ g, const float* __restrict__ be,
    float* __restrict__ statsOut, int M, int NB)
{
    __shared__ double sD[8][128];
    __shared__ double qD[8][128];
    int tid = threadIdx.x;
    int grp = tid >> 7;      // 0..7
    int c = tid & 127;
    double s = 0.0, q = 0.0;
    for (int b = grp; b < NB; b += 8) {
        s += (double)g_part[b * 256 + c];
        q += (double)g_part[b * 256 + 128 + c];
    }
    sD[grp][c] = s; qD[grp][c] = q;
    __syncthreads();
    if (tid < 128) {
        double ss = 0.0, qq = 0.0;
        #pragma unroll
        for (int gg = 0; gg < 8; gg++) { ss += sD[gg][tid]; qq += qD[gg][tid]; }
        double mean = ss / (double)M;
        double var = qq / (double)M - mean * mean;
        float rstd = (float)(1.0 / sqrt(var + 1e-5));
        float scale = g[tid] * rstd;
        statsOut[tid] = scale;
        statsOut[128 + tid] = be[tid] - (float)mean * scale;
    }
}

// ============================ head ==========================================
__global__ __launch_bounds__(128) void k_fc(
    const float* __restrict__ Zlast, const float* __restrict__ stats,
    const float* __restrict__ W1, const float* __restrict__ b1,
    const float* __restrict__ W2, const float* __restrict__ b2,
    float* __restrict__ out, int M)
{
    __shared__ float W1s[64][129];
    __shared__ float ts[128];
    __shared__ float fps[128];
    __shared__ float b1s[64], w2s[64];
    __shared__ float ws[2];

    int tid = threadIdx.x;
    for (int i = tid; i < 64 * 128; i += 128) W1s[i >> 7][i & 127] = W1[i];
    if (tid < 64) { b1s[tid] = b1[tid]; w2s[tid] = W2[tid]; }
    float sc = stats[tid], sh = stats[128 + tid];
    __syncthreads();

    float bias2 = b2[0];
    const int ROWS = 32;
    int r0 = blockIdx.x * ROWS;

    for (int rr = 0; rr < ROWS; rr++) {
        int r = r0 + rr;
        if (r >= M) break;
        float z = Zlast[(size_t)r * HID + tid];
        ts[tid] = lrelu(fmaf(z, sc, sh)) + g_H0[(size_t)r * HID + tid];
        __syncthreads();
        int j = tid & 63;
        int half = (tid >> 6) * 64;
        float fp = 0.f;
        #pragma unroll 16
        for (int k = 0; k < 64; k++) fp += W1s[j][half + k] * ts[half + k];
        fps[tid] = fp;
        __syncthreads();
        if (tid < 64) {
            float f = fps[tid] + fps[tid + 64] + b1s[tid];
            f = lrelu(f);
            float contrib = f * w2s[tid];
            #pragma unroll
            for (int o = 16; o > 0; o >>= 1)
                contrib += __shfl_down_sync(0xffffffff, contrib, o);
            if ((tid & 31) == 0) ws[tid >> 5] = contrib;
        }
        __syncthreads();
        if (tid == 0) out[r] = ws[0] + ws[1] + bias2;
        __syncthreads();
    }
}

// ============================ launch ========================================
extern "C" void kernel_launch(void* const* d_in, const int* in_sizes, int n_in,
                              void* d_out, int out_size)
{
    const float* x    = (const float*)d_in[0];
    const int*   ei   = (const int*)d_in[1];
    const float* W_in = (const float*)d_in[2];
    const float* b_in = (const float*)d_in[3];
    const float* Wl[3] = { (const float*)d_in[4], (const float*)d_in[7], (const float*)d_in[10] };
    const float* bl[3] = { (const float*)d_in[5], (const float*)d_in[8], (const float*)d_in[11] };
    const float* Wr[3] = { (const float*)d_in[6], (const float*)d_in[9], (const float*)d_in[12] };
    const float* gm[3] = { (const float*)d_in[13], (const float*)d_in[15], (const float*)d_in[17] };
    const float* be[3] = { (const float*)d_in[14], (const float*)d_in[16], (const float*)d_in[18] };
    const float* W_fc1 = (const float*)d_in[19];
    const float* b_fc1 = (const float*)d_in[20];
    const float* W_fc2 = (const float*)d_in[21];
    const float* b_fc2 = (const float*)d_in[22];
    float* out = (float*)d_out;

    int M = in_sizes[0] / HID;
    int E = in_sizes[1] / 2;
    const int* src = ei;
    const int* dst = ei + E;

    // device symbol addresses (pure lookups; no allocation)
    void *pH0v, *pAv, *pZv, *pPartv, *pStatsv, *pDegv;
    cudaGetSymbolAddress(&pH0v, g_H0);
    cudaGetSymbolAddress(&pAv, g_A);
    cudaGetSymbolAddress(&pZv, g_Zb);
    cudaGetSymbolAddress(&pPartv, g_part);
    cudaGetSymbolAddress(&pStatsv, g_statsBuf);
    cudaGetSymbolAddress(&pDegv, g_deg);
    float* pH0 = (float*)pH0v;
    float* pA = (float*)pAv;
    float* pZ0 = (float*)pZv;
    float* pZ1 = pZ0 + (size_t)NMAX * HID;
    float* pPart = (float*)pPartv;
    float* pStats0 = (float*)pStatsv;
    float* pStats1 = pStats0 + 256;

    int scanBlocks = (M + 1023) / 1024;
    int gemmGrid = (M + 127) / 128;
    int aggGrid = (M + 7) / 8;

    // ---- CSR build (deterministic for max-agg: order independent)
    cudaMemsetAsync(pDegv, 0, (size_t)M * sizeof(int));
    k_count<<<(E + 511) / 512, 512>>>(dst, E);
    k_scanA<<<scanBlocks, 1024>>>(M);
    k_scanB<<<1, 128>>>(scanBlocks);
    k_scanC<<<(M + 255) / 256, 256>>>(M);
    k_scatter<<<(E + 511) / 512, 512>>>(src, dst, E);

    // ---- input projection: H0 = x @ W_in^T + b_in
    gemm_sage<<<gemmGrid, 256>>>(x, nullptr, nullptr, W_in, nullptr, b_in,
                                 pH0, nullptr, M, 1, 0);

    // ---- layer 1 (input H0, no transform)
    k_agg<<<aggGrid, 256>>>(pH0, nullptr, 0, M);
    gemm_sage<<<gemmGrid, 256>>>(pA, pH0, nullptr, Wl[0], Wr[0], bl[0],
                                 pZ0, pPart, M, 2, 0);
    k_bnfinal<<<1, 1024>>>(gm[0], be[0], pStats0, M, gemmGrid);

    // ---- layer 2 (input = xform(Z0, stats0))
    k_agg<<<aggGrid, 256>>>(pZ0, pStats0, 1, M);
    gemm_sage<<<gemmGrid, 256>>>(pA, pZ0, pStats0, Wl[1], Wr[1], bl[1],
                                 pZ1, pPart, M, 2, 1);
    k_bnfinal<<<1, 1024>>>(gm[1], be[1], pStats1, M, gemmGrid);

    // ---- layer 3 (input = xform(Z1, stats1))
    k_agg<<<aggGrid, 256>>>(pZ1, pStats1, 1, M);
    gemm_sage<<<gemmGrid, 256>>>(pA, pZ1, pStats1, Wl[2], Wr[2], bl[2],
                                 pZ0, pPart, M, 2, 1);
    k_bnfinal<<<1, 1024>>>(gm[2], be[2], pStats0, M, gemmGrid);

    // ---- head: out = lrelu((xform(Z0,stats0) + H0) @ Wfc1^T + b1) @ Wfc2^T + b2
    k_fc<<<(M + 31) / 32, 128>>>(pZ0, pStats0, W_fc1, b_fc1, W_fc2, b_fc2, out, M);
}

// round 3
// speedup vs baseline: 1.0549x; 1.0470x over previous
#include <cuda_runtime.h>
#include <cuda_bf16.h>
#include <stdint.h>

// GraphSAGE max-agg pipeline, fp32, BN fused into GEMM epilogue + consumers.

#define NMAX 100000
#define EMAX 1600000
#define HID 128
#define NEG 0.01f
#define GBMAX 800   // max gemm blocks (ceil(100000/128)=782)

// -------------------- device scratch ---------------------------------------
__device__ float g_H0[NMAX * HID];        // input-proj output == residual
__device__ float g_A [NMAX * HID];        // max-aggregated neighbors
__device__ float g_Zb[2][NMAX * HID];     // ping-pong pre-BN GEMM outputs
__device__ int   g_deg [NMAX];
__device__ int   g_off [NMAX + 1];
__device__ int   g_cur [NMAX];
__device__ int   g_srcs[EMAX];
__device__ float g_part[GBMAX * 256];     // per-gemm-block col sums / sumsq
__device__ float g_statsBuf[2][256];      // [0:128) scale, [128:256) shift
__device__ int   g_bsum[128];

// -------------------- helpers ----------------------------------------------
__device__ __forceinline__ unsigned long long pack_dup(float a) {
    unsigned long long r;
    asm("mov.b64 %0, {%1, %1};" : "=l"(r) : "f"(a));
    return r;
}
__device__ __forceinline__ void fma2(unsigned long long& d,
                                     unsigned long long a, unsigned long long b) {
    asm("fma.rn.f32x2 %0, %1, %2, %0;" : "+l"(d) : "l"(a), "l"(b));
}
union F2u { unsigned long long u; float2 f; };

__device__ __forceinline__ float lrelu(float x) { return fmaxf(x, NEG * x); }

__device__ __forceinline__ float4 xform4(float4 v, float4 sc, float4 sh) {
    v.x = lrelu(fmaf(v.x, sc.x, sh.x));
    v.y = lrelu(fmaf(v.y, sc.y, sh.y));
    v.z = lrelu(fmaf(v.z, sc.z, sh.z));
    v.w = lrelu(fmaf(v.w, sc.w, sh.w));
    return v;
}
__device__ __forceinline__ float4 max4(float4 a, float4 b) {
    a.x = fmaxf(a.x, b.x); a.y = fmaxf(a.y, b.y);
    a.z = fmaxf(a.z, b.z); a.w = fmaxf(a.w, b.w);
    return a;
}

// ============================ CSR construction ==============================
__global__ void k_count(const int* __restrict__ dst, int E) {
    int e = blockIdx.x * blockDim.x + threadIdx.x;
    if (e < E) atomicAdd(&g_deg[dst[e]], 1);
}

__global__ void k_scanA(int M) {
    __shared__ int sh[1024];
    int i = blockIdx.x * 1024 + threadIdx.x;
    int v = (i < M) ? g_deg[i] : 0;
    sh[threadIdx.x] = v;
    __syncthreads();
    #pragma unroll
    for (int d = 1; d < 1024; d <<= 1) {
        int t = (threadIdx.x >= d) ? sh[threadIdx.x - d] : 0;
        __syncthreads();
        sh[threadIdx.x] += t;
        __syncthreads();
    }
    if (i < M) g_off[i + 1] = sh[threadIdx.x];
    if (threadIdx.x == 1023) g_bsum[blockIdx.x] = sh[1023];
}

__global__ void k_scanB(int nb) {  // exclusive scan of <=128 block sums
    int t = threadIdx.x;
    int orig = (t < nb) ? g_bsum[t] : 0;
    int v = orig;
    #pragma unroll
    for (int o = 1; o < 32; o <<= 1) {
        int u = __shfl_up_sync(0xffffffffu, v, o);
        if ((t & 31) >= o) v += u;
    }
    __shared__ int ws[4];
    if ((t & 31) == 31) ws[t >> 5] = v;
    __syncthreads();
    int add = 0;
    #pragma unroll
    for (int w = 0; w < 4; w++) add += (w < (t >> 5)) ? ws[w] : 0;
    v += add;
    if (t < nb) g_bsum[t] = v - orig;  // exclusive
}

__global__ void k_scanC(int M) {
    int i = blockIdx.x * blockDim.x + threadIdx.x;
    if (i < M) {
        int inc = g_off[i + 1] + g_bsum[i >> 10];
        g_off[i + 1] = inc;
        g_cur[i] = inc - g_deg[i];
        if (i == 0) g_off[0] = 0;
    }
}

__global__ void k_scatter(const int* __restrict__ src, const int* __restrict__ dst, int E) {
    int e = blockIdx.x * blockDim.x + threadIdx.x;
    if (e < E) {
        int pos = atomicAdd(&g_cur[dst[e]], 1);
        g_srcs[pos] = src[e];
    }
}

// ============================ max aggregation ===============================
// warp per node, lane = 4 features (float4). Applies BN+lrelu transform of the
// previous layer on the fly (stats!=null).
__global__ __launch_bounds__(256) void k_agg(const float* __restrict__ Hin,
                                             const float* __restrict__ stats,
                                             int hasStats, int M)
{
    int n = blockIdx.x * 8 + (threadIdx.x >> 5);
    if (n >= M) return;
    int lane = threadIdx.x & 31;

    float4 sc, sh;
    if (hasStats) {
        sc = *(const float4*)&stats[lane * 4];
        sh = *(const float4*)&stats[128 + lane * 4];
    }

    int s = g_off[n], e = g_off[n + 1];
    float4 m = make_float4(-3.4e38f, -3.4e38f, -3.4e38f, -3.4e38f);
    int j = s;
    for (; j + 4 <= e; j += 4) {
        int s0 = g_srcs[j], s1 = g_srcs[j + 1], s2 = g_srcs[j + 2], s3 = g_srcs[j + 3];
        float4 v0 = *(const float4*)&Hin[(size_t)s0 * HID + lane * 4];
        float4 v1 = *(const float4*)&Hin[(size_t)s1 * HID + lane * 4];
        float4 v2 = *(const float4*)&Hin[(size_t)s2 * HID + lane * 4];
        float4 v3 = *(const float4*)&Hin[(size_t)s3 * HID + lane * 4];
        if (hasStats) {
            v0 = xform4(v0, sc, sh); v1 = xform4(v1, sc, sh);
            v2 = xform4(v2, sc, sh); v3 = xform4(v3, sc, sh);
        }
        m = max4(m, max4(max4(v0, v1), max4(v2, v3)));
    }
    for (; j < e; ++j) {
        float4 v = *(const float4*)&Hin[(size_t)g_srcs[j] * HID + lane * 4];
        if (hasStats) v = xform4(v, sc, sh);
        m = max4(m, v);
    }
    if (e == s) m = make_float4(0.f, 0.f, 0.f, 0.f);
    *(float4*)&g_A[(size_t)n * HID + lane * 4] = m;
}

// ============================ GEMM (fp32, f32x2 FMA) ========================
// Zout := A0 @ W0^T (+ xform(A1) @ W1^T) + bias ; optional per-block BN partials.
__global__ __launch_bounds__(256) void gemm_sage(
    const float* __restrict__ A0,
    const float* __restrict__ A1,
    const float* __restrict__ prevStats,
    const float* __restrict__ W0,
    const float* __restrict__ W1,
    const float* __restrict__ bias,
    float* __restrict__ Zout,
    float* __restrict__ part,
    int M, int nm, int hasStats)
{
    __shared__ float As[16][132];
    __shared__ float Ws[16][132];
    __shared__ float scs[128], shs[128];

    int tid = threadIdx.x;
    int tx = tid & 15;      // col block: tx*8
    int ty = tid >> 4;      // row block: ty*8
    int m0 = blockIdx.x * 128;

    int lr = tid >> 2;          // 0..63 (row)
    int lc = (tid & 3) << 2;    // 0,4,8,12 (k col group)

    if (hasStats) {
        if (tid < 128) { scs[tid] = prevStats[tid]; shs[tid] = prevStats[128 + tid]; }
        __syncthreads();
    }

    unsigned long long acc2[8][4];
    #pragma unroll
    for (int i = 0; i < 8; i++)
        #pragma unroll
        for (int j = 0; j < 4; j++) acc2[i][j] = 0ull;

    const float* Amats[2] = { A0, A1 };
    const float* Wmats[2] = { W0, W1 };

    for (int mm = 0; mm < nm; ++mm) {
        const float* __restrict__ A = Amats[mm];
        const float* __restrict__ W = Wmats[mm];
        int doX = (mm == 1) && hasStats;
        for (int k0 = 0; k0 < 128; k0 += 16) {
            #pragma unroll
            for (int h = 0; h < 2; ++h) {
                int row = lr + h * 64;
                int gm = m0 + row;
                float4 v = (gm < M) ? *(const float4*)&A[(size_t)gm * HID + k0 + lc]
                                    : make_float4(0.f, 0.f, 0.f, 0.f);
                if (doX) {
                    v.x = lrelu(fmaf(v.x, scs[k0 + lc + 0], shs[k0 + lc + 0]));
                    v.y = lrelu(fmaf(v.y, scs[k0 + lc + 1], shs[k0 + lc + 1]));
                    v.z = lrelu(fmaf(v.z, scs[k0 + lc + 2], shs[k0 + lc + 2]));
                    v.w = lrelu(fmaf(v.w, scs[k0 + lc + 3], shs[k0 + lc + 3]));
                }
                As[lc + 0][row] = v.x; As[lc + 1][row] = v.y;
                As[lc + 2][row] = v.z; As[lc + 3][row] = v.w;
            }
            #pragma unroll
            for (int h = 0; h < 2; ++h) {
                int n = lr + h * 64;
                float4 v = *(const float4*)&W[n * HID + k0 + lc];
                Ws[lc + 0][n] = v.x; Ws[lc + 1][n] = v.y;
                Ws[lc + 2][n] = v.z; Ws[lc + 3][n] = v.w;
            }
            __syncthreads();
            #pragma unroll
            for (int kk = 0; kk < 16; ++kk) {
                float a[8];
                *(float4*)&a[0] = *(const float4*)&As[kk][ty * 8];
                *(float4*)&a[4] = *(const float4*)&As[kk][ty * 8 + 4];
                longlong2 bb0 = *(const longlong2*)&Ws[kk][tx * 8];
                longlong2 bb1 = *(const longlong2*)&Ws[kk][tx * 8 + 4];
                unsigned long long b2[4] = {
                    (unsigned long long)bb0.x, (unsigned long long)bb0.y,
                    (unsigned long long)bb1.x, (unsigned long long)bb1.y };
                #pragma unroll
                for (int i = 0; i < 8; i++) {
                    unsigned long long av = pack_dup(a[i]);
                    fma2(acc2[i][0], av, b2[0]);
                    fma2(acc2[i][1], av, b2[1]);
                    fma2(acc2[i][2], av, b2[2]);
                    fma2(acc2[i][3], av, b2[3]);
                }
            }
            __syncthreads();
        }
    }

    float bv[8];
    *(float4*)&bv[0] = *(const float4*)&bias[tx * 8];
    *(float4*)&bv[4] = *(const float4*)&bias[tx * 8 + 4];

    float colS[8] = {0,0,0,0,0,0,0,0};
    float colQ[8] = {0,0,0,0,0,0,0,0};

    #pragma unroll
    for (int i = 0; i < 8; i++) {
        int gm = m0 + ty * 8 + i;
        if (gm < M) {
            F2u u0, u1, u2, u3;
            u0.u = acc2[i][0]; u1.u = acc2[i][1]; u2.u = acc2[i][2]; u3.u = acc2[i][3];
            float o[8] = { u0.f.x + bv[0], u0.f.y + bv[1], u1.f.x + bv[2], u1.f.y + bv[3],
                           u2.f.x + bv[4], u2.f.y + bv[5], u3.f.x + bv[6], u3.f.y + bv[7] };
            *(float4*)&Zout[(size_t)gm * HID + tx * 8]     = *(float4*)&o[0];
            *(float4*)&Zout[(size_t)gm * HID + tx * 8 + 4] = *(float4*)&o[4];
            #pragma unroll
            for (int j = 0; j < 8; j++) { colS[j] += o[j]; colQ[j] += o[j] * o[j]; }
        }
    }

    if (part) {
        __syncthreads();   // re-use As/Ws
        #pragma unroll
        for (int j = 0; j < 8; j++) {
            As[ty][tx * 8 + j] = colS[j];
            Ws[ty][tx * 8 + j] = colQ[j];
        }
        __syncthreads();
        if (tid < 128) {
            float s = 0.f, q = 0.f;
            #pragma unroll
            for (int t2 = 0; t2 < 16; t2++) { s += As[t2][tid]; q += Ws[t2][tid]; }
            part[blockIdx.x * 256 + tid] = s;
            part[blockIdx.x * 256 + 128 + tid] = q;
        }
    }
}

// ============================ BN stats finalize =============================
__global__ __launch_bounds__(1024) void k_bnfinal(
    const float* __restrict__ g, const float* __restrict__ be,
    float* __restrict__ statsOut, int M, int NB)
{
    __shared__ double sD[8][128];
    __shared__ double qD[8][128];
    int tid = threadIdx.x;
    int grp = tid >> 7;      // 0..7
    int c = tid & 127;
    double s = 0.0, q = 0.0;
    for (int b = grp; b < NB; b += 8) {
        s += (double)g_part[b * 256 + c];
        q += (double)g_part[b * 256 + 128 + c];
    }
    sD[grp][c] = s; qD[grp][c] = q;
    __syncthreads();
    if (tid < 128) {
        double ss = 0.0, qq = 0.0;
        #pragma unroll
        for (int gg = 0; gg < 8; gg++) { ss += sD[gg][tid]; qq += qD[gg][tid]; }
        double mean = ss / (double)M;
        double var = qq / (double)M - mean * mean;
        float rstd = (float)(1.0 / sqrt(var + 1e-5));
        float scale = g[tid] * rstd;
        statsOut[tid] = scale;
        statsOut[128 + tid] = be[tid] - (float)mean * scale;
    }
}

// ============================ head (warp per row) ===========================
// out[r] = lrelu((xform(Z[r]) + H0[r]) @ W1^T + b1) @ W2^T + b2
__global__ __launch_bounds__(256) void k_fc(
    const float* __restrict__ Zlast, const float* __restrict__ stats,
    const float* __restrict__ W1, const float* __restrict__ b1,
    const float* __restrict__ W2, const float* __restrict__ b2,
    float* __restrict__ out, int M)
{
    __shared__ float W1s[64][132];     // padded: conflict-free per quarter-warp
    __shared__ float b1s[64], w2s[64];
    __shared__ float xsh[8][128];      // one row buffer per warp

    int tid = threadIdx.x;
    int wid = tid >> 5;
    int lane = tid & 31;

    for (int i = tid; i < 64 * 128; i += 256) W1s[i >> 7][i & 127] = W1[i];
    if (tid < 64) { b1s[tid] = b1[tid]; w2s[tid] = W2[tid]; }
    __syncthreads();

    float4 sc = *(const float4*)&stats[lane * 4];
    float4 sh = *(const float4*)&stats[128 + lane * 4];
    float bias2 = b2[0];
    float w2a = w2s[lane], w2b = w2s[lane + 32];
    float b1a = b1s[lane], b1b = b1s[lane + 32];

    const int ROWS = 8;                // rows per warp
    int rbase = blockIdx.x * (8 * ROWS) + wid * ROWS;

    for (int rr = 0; rr < ROWS; rr++) {
        int r = rbase + rr;
        if (r >= M) return;
        // stage transformed row into shared
        float4 z = *(const float4*)&Zlast[(size_t)r * HID + lane * 4];
        float4 h = *(const float4*)&g_H0[(size_t)r * HID + lane * 4];
        z = xform4(z, sc, sh);
        z.x += h.x; z.y += h.y; z.z += h.z; z.w += h.w;
        *(float4*)&xsh[wid][lane * 4] = z;
        __syncwarp();

        float acc0 = 0.f, acc1 = 0.f;
        #pragma unroll
        for (int k = 0; k < 128; k += 4) {
            float4 xv = *(const float4*)&xsh[wid][k];
            float4 w0 = *(const float4*)&W1s[lane][k];
            float4 w1 = *(const float4*)&W1s[lane + 32][k];
            acc0 = fmaf(xv.x, w0.x, acc0); acc0 = fmaf(xv.y, w0.y, acc0);
            acc0 = fmaf(xv.z, w0.z, acc0); acc0 = fmaf(xv.w, w0.w, acc0);
            acc1 = fmaf(xv.x, w1.x, acc1); acc1 = fmaf(xv.y, w1.y, acc1);
            acc1 = fmaf(xv.z, w1.z, acc1); acc1 = fmaf(xv.w, w1.w, acc1);
        }
        float f0 = lrelu(acc0 + b1a);
        float f1 = lrelu(acc1 + b1b);
        float contrib = f0 * w2a + f1 * w2b;
        #pragma unroll
        for (int o = 16; o > 0; o >>= 1)
            contrib += __shfl_down_sync(0xffffffffu, contrib, o);
        if (lane == 0) out[r] = contrib + bias2;
        __syncwarp();
    }
}

// ============================ launch ========================================
extern "C" void kernel_launch(void* const* d_in, const int* in_sizes, int n_in,
                              void* d_out, int out_size)
{
    const float* x    = (const float*)d_in[0];
    const int*   ei   = (const int*)d_in[1];
    const float* W_in = (const float*)d_in[2];
    const float* b_in = (const float*)d_in[3];
    const float* Wl[3] = { (const float*)d_in[4], (const float*)d_in[7], (const float*)d_in[10] };
    const float* bl[3] = { (const float*)d_in[5], (const float*)d_in[8], (const float*)d_in[11] };
    const float* Wr[3] = { (const float*)d_in[6], (const float*)d_in[9], (const float*)d_in[12] };
    const float* gm[3] = { (const float*)d_in[13], (const float*)d_in[15], (const float*)d_in[17] };
    const float* be[3] = { (const float*)d_in[14], (const float*)d_in[16], (const float*)d_in[18] };
    const float* W_fc1 = (const float*)d_in[19];
    const float* b_fc1 = (const float*)d_in[20];
    const float* W_fc2 = (const float*)d_in[21];
    const float* b_fc2 = (const float*)d_in[22];
    float* out = (float*)d_out;

    int M = in_sizes[0] / HID;
    int E = in_sizes[1] / 2;
    const int* src = ei;
    const int* dst = ei + E;

    void *pH0v, *pAv, *pZv, *pPartv, *pStatsv, *pDegv;
    cudaGetSymbolAddress(&pH0v, g_H0);
    cudaGetSymbolAddress(&pAv, g_A);
    cudaGetSymbolAddress(&pZv, g_Zb);
    cudaGetSymbolAddress(&pPartv, g_part);
    cudaGetSymbolAddress(&pStatsv, g_statsBuf);
    cudaGetSymbolAddress(&pDegv, g_deg);
    float* pH0 = (float*)pH0v;
    float* pA = (float*)pAv;
    float* pZ0 = (float*)pZv;
    float* pZ1 = pZ0 + (size_t)NMAX * HID;
    float* pPart = (float*)pPartv;
    float* pStats0 = (float*)pStatsv;
    float* pStats1 = pStats0 + 256;

    int scanBlocks = (M + 1023) / 1024;
    int gemmGrid = (M + 127) / 128;
    int aggGrid = (M + 7) / 8;

    // ---- CSR build, with the input-proj GEMM interleaved as the 4th kernel
    //      launch (ncu -s5 -c1 captures the 4th kernel: we want the GEMM).
    cudaMemsetAsync(pDegv, 0, (size_t)M * sizeof(int));
    k_count<<<(E + 511) / 512, 512>>>(dst, E);                          // 1
    k_scanA<<<scanBlocks, 1024>>>(M);                                   // 2
    k_scanB<<<1, 128>>>(scanBlocks);                                    // 3
    // independent of CSR: H0 = x @ W_in^T + b_in
    gemm_sage<<<gemmGrid, 256>>>(x, nullptr, nullptr, W_in, nullptr,    // 4 (profiled)
                                 b_in, pH0, nullptr, M, 1, 0);
    k_scanC<<<(M + 255) / 256, 256>>>(M);                               // 5
    k_scatter<<<(E + 511) / 512, 512>>>(src, dst, E);                   // 6

    // ---- layer 1 (input H0, no transform)
    k_agg<<<aggGrid, 256>>>(pH0, nullptr, 0, M);
    gemm_sage<<<gemmGrid, 256>>>(pA, pH0, nullptr, Wl[0], Wr[0], bl[0],
                                 pZ0, pPart, M, 2, 0);
    k_bnfinal<<<1, 1024>>>(gm[0], be[0], pStats0, M, gemmGrid);

    // ---- layer 2 (input = xform(Z0, stats0))
    k_agg<<<aggGrid, 256>>>(pZ0, pStats0, 1, M);
    gemm_sage<<<gemmGrid, 256>>>(pA, pZ0, pStats0, Wl[1], Wr[1], bl[1],
                                 pZ1, pPart, M, 2, 1);
    k_bnfinal<<<1, 1024>>>(gm[1], be[1], pStats1, M, gemmGrid);

    // ---- layer 3 (input = xform(Z1, stats1))
    k_agg<<<aggGrid, 256>>>(pZ1, pStats1, 1, M);
    gemm_sage<<<gemmGrid, 256>>>(pA, pZ1, pStats1, Wl[2], Wr[2], bl[2],
                                 pZ0, pPart, M, 2, 1);
    k_bnfinal<<<1, 1024>>>(gm[2], be[2], pStats0, M, gemmGrid);

    // ---- head
    k_fc<<<(M + 63) / 64, 256>>>(pZ0, pStats0, W_fc1, b_fc1, W_fc2, b_fc2, out, M);
}

// round 4
// speedup vs baseline: 1.1080x; 1.0503x over previous
#include <cuda_runtime.h>
#include <cuda_bf16.h>
#include <stdint.h>

// GraphSAGE max-agg pipeline, fp32, BN fused into GEMM epilogue + consumers.
// R4: software-pipelined GEMM (ping-pong smem, 1 barrier/chunk, prefetch).

#define NMAX 100000
#define EMAX 1600000
#define HID 128
#define NEG 0.01f
#define GBMAX 800

// -------------------- device scratch ---------------------------------------
__device__ float g_H0[NMAX * HID];
__device__ float g_A [NMAX * HID];
__device__ float g_Zb[2][NMAX * HID];
__device__ int   g_deg [NMAX];
__device__ int   g_off [NMAX + 1];
__device__ int   g_cur [NMAX];
__device__ int   g_srcs[EMAX];
__device__ float g_part[GBMAX * 256];
__device__ float g_statsBuf[2][256];
__device__ int   g_bsum[128];

// -------------------- helpers ----------------------------------------------
__device__ __forceinline__ unsigned long long pack_dup(float a) {
    unsigned long long r;
    asm("mov.b64 %0, {%1, %1};" : "=l"(r) : "f"(a));
    return r;
}
__device__ __forceinline__ void fma2(unsigned long long& d,
                                     unsigned long long a, unsigned long long b) {
    asm("fma.rn.f32x2 %0, %1, %2, %0;" : "+l"(d) : "l"(a), "l"(b));
}
union F2u { unsigned long long u; float2 f; };

__device__ __forceinline__ float lrelu(float x) { return fmaxf(x, NEG * x); }

__device__ __forceinline__ float4 xform4(float4 v, float4 sc, float4 sh) {
    v.x = lrelu(fmaf(v.x, sc.x, sh.x));
    v.y = lrelu(fmaf(v.y, sc.y, sh.y));
    v.z = lrelu(fmaf(v.z, sc.z, sh.z));
    v.w = lrelu(fmaf(v.w, sc.w, sh.w));
    return v;
}
__device__ __forceinline__ float4 max4(float4 a, float4 b) {
    a.x = fmaxf(a.x, b.x); a.y = fmaxf(a.y, b.y);
    a.z = fmaxf(a.z, b.z); a.w = fmaxf(a.w, b.w);
    return a;
}

// ============================ CSR construction ==============================
__global__ void k_count(const int* __restrict__ dst, int E) {
    int e = blockIdx.x * blockDim.x + threadIdx.x;
    if (e < E) atomicAdd(&g_deg[dst[e]], 1);
}

__global__ void k_scanA(int M) {
    __shared__ int sh[1024];
    int i = blockIdx.x * 1024 + threadIdx.x;
    int v = (i < M) ? g_deg[i] : 0;
    sh[threadIdx.x] = v;
    __syncthreads();
    #pragma unroll
    for (int d = 1; d < 1024; d <<= 1) {
        int t = (threadIdx.x >= d) ? sh[threadIdx.x - d] : 0;
        __syncthreads();
        sh[threadIdx.x] += t;
        __syncthreads();
    }
    if (i < M) g_off[i + 1] = sh[threadIdx.x];
    if (threadIdx.x == 1023) g_bsum[blockIdx.x] = sh[1023];
}

__global__ void k_scanB(int nb) {
    int t = threadIdx.x;
    int orig = (t < nb) ? g_bsum[t] : 0;
    int v = orig;
    #pragma unroll
    for (int o = 1; o < 32; o <<= 1) {
        int u = __shfl_up_sync(0xffffffffu, v, o);
        if ((t & 31) >= o) v += u;
    }
    __shared__ int ws[4];
    if ((t & 31) == 31) ws[t >> 5] = v;
    __syncthreads();
    int add = 0;
    #pragma unroll
    for (int w = 0; w < 4; w++) add += (w < (t >> 5)) ? ws[w] : 0;
    v += add;
    if (t < nb) g_bsum[t] = v - orig;
}

__global__ void k_scanC(int M) {
    int i = blockIdx.x * blockDim.x + threadIdx.x;
    if (i < M) {
        int inc = g_off[i + 1] + g_bsum[i >> 10];
        g_off[i + 1] = inc;
        g_cur[i] = inc - g_deg[i];
        if (i == 0) g_off[0] = 0;
    }
}

__global__ void k_scatter(const int* __restrict__ src, const int* __restrict__ dst, int E) {
    int e = blockIdx.x * blockDim.x + threadIdx.x;
    if (e < E) {
        int pos = atomicAdd(&g_cur[dst[e]], 1);
        g_srcs[pos] = src[e];
    }
}

// ============================ max aggregation ===============================
__global__ __launch_bounds__(256) void k_agg(const float* __restrict__ Hin,
                                             const float* __restrict__ stats,
                                             int hasStats, int M)
{
    int n = blockIdx.x * 8 + (threadIdx.x >> 5);
    if (n >= M) return;
    int lane = threadIdx.x & 31;

    float4 sc, sh;
    if (hasStats) {
        sc = *(const float4*)&stats[lane * 4];
        sh = *(const float4*)&stats[128 + lane * 4];
    }

    int s = g_off[n], e = g_off[n + 1];
    float4 m = make_float4(-3.4e38f, -3.4e38f, -3.4e38f, -3.4e38f);
    int j = s;
    for (; j + 4 <= e; j += 4) {
        int s0 = g_srcs[j], s1 = g_srcs[j + 1], s2 = g_srcs[j + 2], s3 = g_srcs[j + 3];
        float4 v0 = *(const float4*)&Hin[(size_t)s0 * HID + lane * 4];
        float4 v1 = *(const float4*)&Hin[(size_t)s1 * HID + lane * 4];
        float4 v2 = *(const float4*)&Hin[(size_t)s2 * HID + lane * 4];
        float4 v3 = *(const float4*)&Hin[(size_t)s3 * HID + lane * 4];
        if (hasStats) {
            v0 = xform4(v0, sc, sh); v1 = xform4(v1, sc, sh);
            v2 = xform4(v2, sc, sh); v3 = xform4(v3, sc, sh);
        }
        m = max4(m, max4(max4(v0, v1), max4(v2, v3)));
    }
    for (; j < e; ++j) {
        float4 v = *(const float4*)&Hin[(size_t)g_srcs[j] * HID + lane * 4];
        if (hasStats) v = xform4(v, sc, sh);
        m = max4(m, v);
    }
    if (e == s) m = make_float4(0.f, 0.f, 0.f, 0.f);
    *(float4*)&g_A[(size_t)n * HID + lane * 4] = m;
}

// ============================ GEMM (fp32, f32x2, pipelined) =================
// Zout := A0 @ W0^T (+ xform(A1) @ W1^T) + bias ; optional BN partials.
__global__ __launch_bounds__(256, 2) void gemm_sage(
    const float* __restrict__ A0,
    const float* __restrict__ A1,
    const float* __restrict__ prevStats,
    const float* __restrict__ W0,
    const float* __restrict__ W1,
    const float* __restrict__ bias,
    float* __restrict__ Zout,
    float* __restrict__ part,
    int M, int nm, int hasStats)
{
    __shared__ float As[2][16][132];
    __shared__ float Ws[2][16][132];
    __shared__ float scs[128], shs[128];

    int tid = threadIdx.x;
    int tx = tid & 15;
    int ty = tid >> 4;
    int m0 = blockIdx.x * 128;

    int lr = tid >> 2;          // 0..63
    int lc = (tid & 3) << 2;    // 0,4,8,12

    if (hasStats) {
        if (tid < 128) { scs[tid] = prevStats[tid]; shs[tid] = prevStats[128 + tid]; }
        __syncthreads();
    }

    unsigned long long acc2[8][4];
    #pragma unroll
    for (int i = 0; i < 8; i++)
        #pragma unroll
        for (int j = 0; j < 4; j++) acc2[i][j] = 0ull;

    const float* Amats[2] = { A0, A1 };
    const float* Wmats[2] = { W0, W1 };
    int nchunks = nm * 8;   // chunk c: matrix c>>3, k0 = (c&7)*16

    int gm0 = m0 + lr;
    int gm1 = m0 + lr + 64;
    bool ok0 = gm0 < M, ok1 = gm1 < M;

    float4 va0, va1, vw0, vw1;

    // ---- prologue: load chunk 0
    {
        const float* A = Amats[0];
        const float* W = Wmats[0];
        va0 = ok0 ? *(const float4*)&A[(size_t)gm0 * HID + lc] : make_float4(0,0,0,0);
        va1 = ok1 ? *(const float4*)&A[(size_t)gm1 * HID + lc] : make_float4(0,0,0,0);
        vw0 = *(const float4*)&W[(size_t)lr * HID + lc];
        vw1 = *(const float4*)&W[(size_t)(lr + 64) * HID + lc];
    }

    for (int c = 0; c < nchunks; ++c) {
        int buf = c & 1;
        // store staged regs for chunk c into smem[buf]
        {
            float4 a0 = va0, a1 = va1;
            if ((c >> 3) == 1 && hasStats) {
                int kb = (c & 7) * 16 + lc;
                float4 sc4 = *(const float4*)&scs[kb];
                float4 sh4 = *(const float4*)&shs[kb];
                a0 = xform4(a0, sc4, sh4);
                a1 = xform4(a1, sc4, sh4);
            }
            As[buf][lc + 0][lr] = a0.x; As[buf][lc + 1][lr] = a0.y;
            As[buf][lc + 2][lr] = a0.z; As[buf][lc + 3][lr] = a0.w;
            As[buf][lc + 0][lr + 64] = a1.x; As[buf][lc + 1][lr + 64] = a1.y;
            As[buf][lc + 2][lr + 64] = a1.z; As[buf][lc + 3][lr + 64] = a1.w;
            Ws[buf][lc + 0][lr] = vw0.x; Ws[buf][lc + 1][lr] = vw0.y;
            Ws[buf][lc + 2][lr] = vw0.z; Ws[buf][lc + 3][lr] = vw0.w;
            Ws[buf][lc + 0][lr + 64] = vw1.x; Ws[buf][lc + 1][lr + 64] = vw1.y;
            Ws[buf][lc + 2][lr + 64] = vw1.z; Ws[buf][lc + 3][lr + 64] = vw1.w;
        }
        __syncthreads();

        // prefetch chunk c+1 (overlaps with compute below)
        if (c + 1 < nchunks) {
            const float* A = Amats[(c + 1) >> 3];
            const float* W = Wmats[(c + 1) >> 3];
            int k0 = ((c + 1) & 7) * 16;
            va0 = ok0 ? *(const float4*)&A[(size_t)gm0 * HID + k0 + lc] : make_float4(0,0,0,0);
            va1 = ok1 ? *(const float4*)&A[(size_t)gm1 * HID + k0 + lc] : make_float4(0,0,0,0);
            vw0 = *(const float4*)&W[(size_t)lr * HID + k0 + lc];
            vw1 = *(const float4*)&W[(size_t)(lr + 64) * HID + k0 + lc];
        }

        // compute chunk c from smem[buf]
        #pragma unroll
        for (int kk = 0; kk < 16; ++kk) {
            float a[8];
            *(float4*)&a[0] = *(const float4*)&As[buf][kk][ty * 8];
            *(float4*)&a[4] = *(const float4*)&As[buf][kk][ty * 8 + 4];
            longlong2 bb0 = *(const longlong2*)&Ws[buf][kk][tx * 8];
            longlong2 bb1 = *(const longlong2*)&Ws[buf][kk][tx * 8 + 4];
            unsigned long long b2[4] = {
                (unsigned long long)bb0.x, (unsigned long long)bb0.y,
                (unsigned long long)bb1.x, (unsigned long long)bb1.y };
            #pragma unroll
            for (int i = 0; i < 8; i++) {
                unsigned long long av = pack_dup(a[i]);
                fma2(acc2[i][0], av, b2[0]);
                fma2(acc2[i][1], av, b2[1]);
                fma2(acc2[i][2], av, b2[2]);
                fma2(acc2[i][3], av, b2[3]);
            }
        }
        // one barrier per chunk: next iteration writes smem[buf^1], whose last
        // readers were in iteration c-1, already separated by this barrier.
        __syncthreads();
    }

    float bv[8];
    *(float4*)&bv[0] = *(const float4*)&bias[tx * 8];
    *(float4*)&bv[4] = *(const float4*)&bias[tx * 8 + 4];

    float colS[8] = {0,0,0,0,0,0,0,0};
    float colQ[8] = {0,0,0,0,0,0,0,0};

    #pragma unroll
    for (int i = 0; i < 8; i++) {
        int gm = m0 + ty * 8 + i;
        if (gm < M) {
            F2u u0, u1, u2, u3;
            u0.u = acc2[i][0]; u1.u = acc2[i][1]; u2.u = acc2[i][2]; u3.u = acc2[i][3];
            float o[8] = { u0.f.x + bv[0], u0.f.y + bv[1], u1.f.x + bv[2], u1.f.y + bv[3],
                           u2.f.x + bv[4], u2.f.y + bv[5], u3.f.x + bv[6], u3.f.y + bv[7] };
            *(float4*)&Zout[(size_t)gm * HID + tx * 8]     = *(float4*)&o[0];
            *(float4*)&Zout[(size_t)gm * HID + tx * 8 + 4] = *(float4*)&o[4];
            #pragma unroll
            for (int j = 0; j < 8; j++) { colS[j] += o[j]; colQ[j] += o[j] * o[j]; }
        }
    }

    if (part) {
        __syncthreads();
        #pragma unroll
        for (int j = 0; j < 8; j++) {
            As[0][ty][tx * 8 + j] = colS[j];
            Ws[0][ty][tx * 8 + j] = colQ[j];
        }
        __syncthreads();
        if (tid < 128) {
            float s = 0.f, q = 0.f;
            #pragma unroll
            for (int t2 = 0; t2 < 16; t2++) { s += As[0][t2][tid]; q += Ws[0][t2][tid]; }
            part[blockIdx.x * 256 + tid] = s;
            part[blockIdx.x * 256 + 128 + tid] = q;
        }
    }
}

// ============================ BN stats finalize =============================
__global__ __launch_bounds__(1024) void k_bnfinal(
    const float* __restrict__ g, const float* __restrict__ be,
    float* __restrict__ statsOut, int M, int NB)
{
    __shared__ double sD[8][128];
    __shared__ double qD[8][128];
    int tid = threadIdx.x;
    int grp = tid >> 7;
    int c = tid & 127;
    double s = 0.0, q = 0.0;
    for (int b = grp; b < NB; b += 8) {
        s += (double)g_part[b * 256 + c];
        q += (double)g_part[b * 256 + 128 + c];
    }
    sD[grp][c] = s; qD[grp][c] = q;
    __syncthreads();
    if (tid < 128) {
        double ss = 0.0, qq = 0.0;
        #pragma unroll
        for (int gg = 0; gg < 8; gg++) { ss += sD[gg][tid]; qq += qD[gg][tid]; }
        double mean = ss / (double)M;
        double var = qq / (double)M - mean * mean;
        float rstd = (float)(1.0 / sqrt(var + 1e-5));
        float scale = g[tid] * rstd;
        statsOut[tid] = scale;
        statsOut[128 + tid] = be[tid] - (float)mean * scale;
    }
}

// ============================ head (warp per row) ===========================
__global__ __launch_bounds__(256) void k_fc(
    const float* __restrict__ Zlast, const float* __restrict__ stats,
    const float* __restrict__ W1, const float* __restrict__ b1,
    const float* __restrict__ W2, const float* __restrict__ b2,
    float* __restrict__ out, int M)
{
    __shared__ float W1s[64][132];
    __shared__ float b1s[64], w2s[64];
    __shared__ float xsh[8][128];

    int tid = threadIdx.x;
    int wid = tid >> 5;
    int lane = tid & 31;

    for (int i = tid; i < 64 * 128; i += 256) W1s[i >> 7][i & 127] = W1[i];
    if (tid < 64) { b1s[tid] = b1[tid]; w2s[tid] = W2[tid]; }
    __syncthreads();

    float4 sc = *(const float4*)&stats[lane * 4];
    float4 sh = *(const float4*)&stats[128 + lane * 4];
    float bias2 = b2[0];
    float w2a = w2s[lane], w2b = w2s[lane + 32];
    float b1a = b1s[lane], b1b = b1s[lane + 32];

    const int ROWS = 8;
    int rbase = blockIdx.x * (8 * ROWS) + wid * ROWS;

    for (int rr = 0; rr < ROWS; rr++) {
        int r = rbase + rr;
        if (r >= M) return;
        float4 z = *(const float4*)&Zlast[(size_t)r * HID + lane * 4];
        float4 h = *(const float4*)&g_H0[(size_t)r * HID + lane * 4];
        z = xform4(z, sc, sh);
        z.x += h.x; z.y += h.y; z.z += h.z; z.w += h.w;
        *(float4*)&xsh[wid][lane * 4] = z;
        __syncwarp();

        float acc0 = 0.f, acc1 = 0.f;
        #pragma unroll
        for (int k = 0; k < 128; k += 4) {
            float4 xv = *(const float4*)&xsh[wid][k];
            float4 w0 = *(const float4*)&W1s[lane][k];
            float4 w1 = *(const float4*)&W1s[lane + 32][k];
            acc0 = fmaf(xv.x, w0.x, acc0); acc0 = fmaf(xv.y, w0.y, acc0);
            acc0 = fmaf(xv.z, w0.z, acc0); acc0 = fmaf(xv.w, w0.w, acc0);
            acc1 = fmaf(xv.x, w1.x, acc1); acc1 = fmaf(xv.y, w1.y, acc1);
            acc1 = fmaf(xv.z, w1.z, acc1); acc1 = fmaf(xv.w, w1.w, acc1);
        }
        float f0 = lrelu(acc0 + b1a);
        float f1 = lrelu(acc1 + b1b);
        float contrib = f0 * w2a + f1 * w2b;
        #pragma unroll
        for (int o = 16; o > 0; o >>= 1)
            contrib += __shfl_down_sync(0xffffffffu, contrib, o);
        if (lane == 0) out[r] = contrib + bias2;
        __syncwarp();
    }
}

// ============================ launch ========================================
extern "C" void kernel_launch(void* const* d_in, const int* in_sizes, int n_in,
                              void* d_out, int out_size)
{
    const float* x    = (const float*)d_in[0];
    const int*   ei   = (const int*)d_in[1];
    const float* W_in = (const float*)d_in[2];
    const float* b_in = (const float*)d_in[3];
    const float* Wl[3] = { (const float*)d_in[4], (const float*)d_in[7], (const float*)d_in[10] };
    const float* bl[3] = { (const float*)d_in[5], (const float*)d_in[8], (const float*)d_in[11] };
    const float* Wr[3] = { (const float*)d_in[6], (const float*)d_in[9], (const float*)d_in[12] };
    const float* gm[3] = { (const float*)d_in[13], (const float*)d_in[15], (const float*)d_in[17] };
    const float* be[3] = { (const float*)d_in[14], (const float*)d_in[16], (const float*)d_in[18] };
    const float* W_fc1 = (const float*)d_in[19];
    const float* b_fc1 = (const float*)d_in[20];
    const float* W_fc2 = (const float*)d_in[21];
    const float* b_fc2 = (const float*)d_in[22];
    float* out = (float*)d_out;

    int M = in_sizes[0] / HID;
    int E = in_sizes[1] / 2;
    const int* src = ei;
    const int* dst = ei + E;

    void *pH0v, *pAv, *pZv, *pPartv, *pStatsv, *pDegv;
    cudaGetSymbolAddress(&pH0v, g_H0);
    cudaGetSymbolAddress(&pAv, g_A);
    cudaGetSymbolAddress(&pZv, g_Zb);
    cudaGetSymbolAddress(&pPartv, g_part);
    cudaGetSymbolAddress(&pStatsv, g_statsBuf);
    cudaGetSymbolAddress(&pDegv, g_deg);
    float* pH0 = (float*)pH0v;
    float* pA = (float*)pAv;
    float* pZ0 = (float*)pZv;
    float* pZ1 = pZ0 + (size_t)NMAX * HID;
    float* pPart = (float*)pPartv;
    float* pStats0 = (float*)pStatsv;
    float* pStats1 = pStats0 + 256;

    int scanBlocks = (M + 1023) / 1024;
    int gemmGrid = (M + 127) / 128;
    int aggGrid = (M + 7) / 8;

    // ---- CSR build; input-proj GEMM is the 4th launch (ncu target)
    cudaMemsetAsync(pDegv, 0, (size_t)M * sizeof(int));
    k_count<<<(E + 511) / 512, 512>>>(dst, E);                          // 1
    k_scanA<<<scanBlocks, 1024>>>(M);                                   // 2
    k_scanB<<<1, 128>>>(scanBlocks);                                    // 3
    gemm_sage<<<gemmGrid, 256>>>(x, nullptr, nullptr, W_in, nullptr,    // 4 (profiled)
                                 b_in, pH0, nullptr, M, 1, 0);
    k_scanC<<<(M + 255) / 256, 256>>>(M);                               // 5
    k_scatter<<<(E + 511) / 512, 512>>>(src, dst, E);                   // 6

    // ---- layer 1
    k_agg<<<aggGrid, 256>>>(pH0, nullptr, 0, M);
    gemm_sage<<<gemmGrid, 256>>>(pA, pH0, nullptr, Wl[0], Wr[0], bl[0],
                                 pZ0, pPart, M, 2, 0);
    k_bnfinal<<<1, 1024>>>(gm[0], be[0], pStats0, M, gemmGrid);

    // ---- layer 2
    k_agg<<<aggGrid, 256>>>(pZ0, pStats0, 1, M);
    gemm_sage<<<gemmGrid, 256>>>(pA, pZ0, pStats0, Wl[1], Wr[1], bl[1],
                                 pZ1, pPart, M, 2, 1);
    k_bnfinal<<<1, 1024>>>(gm[1], be[1], pStats1, M, gemmGrid);

    // ---- layer 3
    k_agg<<<aggGrid, 256>>>(pZ1, pStats1, 1, M);
    gemm_sage<<<gemmGrid, 256>>>(pA, pZ1, pStats1, Wl[2], Wr[2], bl[2],
                                 pZ0, pPart, M, 2, 1);
    k_bnfinal<<<1, 1024>>>(gm[2], be[2], pStats0, M, gemmGrid);

    // ---- head
    k_fc<<<(M + 63) / 64, 256>>>(pZ0, pStats0, W_fc1, b_fc1, W_fc2, b_fc2, out, M);
}

// round 6
// speedup vs baseline: 1.2338x; 1.1136x over previous
#include <cuda_runtime.h>
#include <cuda_bf16.h>
#include <stdint.h>

// GraphSAGE max-agg pipeline. R6: GEMMs via warp-level mma.sync bf16 (HMMA),
// 3-pass split precision (hi/lo bf16), fp32 accum. BN fused into GEMM
// epilogue + consumers. (tcgen05 unavailable: harness PTX targets compute_103.)

#define NMAX 100000
#define EMAX 1600000
#define HID 128
#define NEG 0.01f
#define GBMAX 800

#define PADK 136                     // bf16 elems per smem row (272 B stride)
#define ABYTES (128 * PADK * 2)      // one 128x128 bf16 tile, padded
#define SM_GEMM_TOTAL (2048 + 4 * ABYTES)

// -------------------- device scratch ---------------------------------------
__device__ float g_H0[NMAX * HID];
__device__ float g_A [NMAX * HID];
__device__ float g_Zb[2][NMAX * HID];
__device__ int   g_deg [NMAX];
__device__ int   g_off [NMAX + 1];
__device__ int   g_cur [NMAX];
__device__ int   g_srcs[EMAX];
__device__ float g_part[GBMAX * 256];
__device__ float g_statsBuf[2][256];
__device__ int   g_bsum[128];

// -------------------- helpers ----------------------------------------------
__device__ __forceinline__ float lrelu(float x) { return fmaxf(x, NEG * x); }

__device__ __forceinline__ float4 xform4(float4 v, float4 sc, float4 sh) {
    v.x = lrelu(fmaf(v.x, sc.x, sh.x));
    v.y = lrelu(fmaf(v.y, sc.y, sh.y));
    v.z = lrelu(fmaf(v.z, sc.z, sh.z));
    v.w = lrelu(fmaf(v.w, sc.w, sh.w));
    return v;
}
__device__ __forceinline__ float4 max4(float4 a, float4 b) {
    a.x = fmaxf(a.x, b.x); a.y = fmaxf(a.y, b.y);
    a.z = fmaxf(a.z, b.z); a.w = fmaxf(a.w, b.w);
    return a;
}

__device__ __forceinline__ void mma16816(float* c, const uint32_t* a,
                                         const uint32_t* b) {
    asm volatile(
        "mma.sync.aligned.m16n8k16.row.col.f32.bf16.bf16.f32 "
        "{%0,%1,%2,%3}, {%4,%5,%6,%7}, {%8,%9}, {%0,%1,%2,%3};"
        : "+f"(c[0]), "+f"(c[1]), "+f"(c[2]), "+f"(c[3])
        : "r"(a[0]), "r"(a[1]), "r"(a[2]), "r"(a[3]), "r"(b[0]), "r"(b[1]));
}

// stage a [128 x 128] f32 tile as hi/lo bf16 into padded row-major smem
__device__ __forceinline__ void stage_bf16(
    const float* __restrict__ G, int row0, int rowLimit,
    const float* __restrict__ scs, const float* __restrict__ shs,
    char* __restrict__ hi, char* __restrict__ lo, int tid)
{
    int r = tid >> 1;
    int ch = (tid & 1) << 6;
    int grow = row0 + r;
    bool valid = grow < rowLimit;
    const float* gp = G + (size_t)grow * HID;
    #pragma unroll
    for (int g8 = 0; g8 < 8; g8++) {
        int colb = ch + g8 * 8;
        float a[8];
        if (valid) {
            *(float4*)&a[0] = *(const float4*)(gp + colb);
            *(float4*)&a[4] = *(const float4*)(gp + colb + 4);
        } else {
            #pragma unroll
            for (int i = 0; i < 8; i++) a[i] = 0.f;
        }
        if (scs) {
            #pragma unroll
            for (int i = 0; i < 8; i++)
                a[i] = lrelu(fmaf(a[i], scs[colb + i], shs[colb + i]));
        }
        uint32_t h4[4], l4[4];
        #pragma unroll
        for (int i = 0; i < 4; i++) {
            __nv_bfloat16 h0 = __float2bfloat16(a[2 * i]);
            __nv_bfloat16 h1 = __float2bfloat16(a[2 * i + 1]);
            float l0 = a[2 * i]     - __bfloat162float(h0);
            float l1 = a[2 * i + 1] - __bfloat162float(h1);
            __nv_bfloat162 hp; hp.x = h0; hp.y = h1;
            __nv_bfloat162 lp; lp.x = __float2bfloat16(l0); lp.y = __float2bfloat16(l1);
            h4[i] = *(uint32_t*)&hp;
            l4[i] = *(uint32_t*)&lp;
        }
        size_t off = ((size_t)r * PADK + colb) * 2;
        *(uint4*)(hi + off) = make_uint4(h4[0], h4[1], h4[2], h4[3]);
        *(uint4*)(lo + off) = make_uint4(l4[0], l4[1], l4[2], l4[3]);
    }
}

// ============================ HMMA GEMM =====================================
// Zout := A0 @ W0^T (+ xform(A1) @ W1^T) + bias ; optional BN partials.
// smem: [0:1024) stats, [1024:1536) bias, [2048:...) Ahi|Alo|Whi|Wlo.
// scratch for BN partials aliases Ahi after the final barrier.
__global__ __launch_bounds__(256, 1) void gemm_mma(
    const float* __restrict__ A0,
    const float* __restrict__ A1,
    const float* __restrict__ prevStats,
    const float* __restrict__ W0,
    const float* __restrict__ W1,
    const float* __restrict__ bias,
    float* __restrict__ Zout,
    float* __restrict__ part,
    int M, int nm, int hasStats)
{
    extern __shared__ char smem[];
    float* sstats = (float*)smem;
    float* sbias  = (float*)(smem + 1024);
    char* Ahi = smem + 2048;
    char* Alo = Ahi + ABYTES;
    char* Whi = Alo + ABYTES;
    char* Wlo = Whi + ABYTES;
    float* scr = (float*)(smem + 2048);   // 1024 floats, aliases Ahi

    int tid = threadIdx.x;
    int wid = tid >> 5;
    int lane = tid & 31;
    int m0 = blockIdx.x * 128;

    if (tid < 128) sbias[tid] = bias[tid];
    if (hasStats && tid < 256) sstats[tid] = prevStats[tid];
    __syncthreads();

    int mw = wid & 3;          // m block: mw*32
    int nw = wid >> 2;         // n block: nw*64
    int g = lane >> 2;         // 0..7
    int t = lane & 3;          // 0..3

    float acc[2][8][4];
    #pragma unroll
    for (int mt = 0; mt < 2; mt++)
        #pragma unroll
        for (int nt = 0; nt < 8; nt++)
            #pragma unroll
            for (int i = 0; i < 4; i++) acc[mt][nt][i] = 0.f;

    for (int pair = 0; pair < nm; pair++) {
        const float* Ap = pair ? A1 : A0;
        const float* Wp = pair ? W1 : W0;
        stage_bf16(Ap, m0, M, (pair && hasStats) ? sstats : nullptr,
                   sstats + 128, Ahi, Alo, tid);
        stage_bf16(Wp, 0, 128, nullptr, nullptr, Whi, Wlo, tid);
        __syncthreads();

        #pragma unroll 2
        for (int ks = 0; ks < 8; ks++) {
            int k0 = ks * 16;
            uint32_t ah[2][4], al[2][4], bh[8][2], bl[8][2];
            #pragma unroll
            for (int mt = 0; mt < 2; mt++) {
                int r = mw * 32 + mt * 16 + g;
                size_t o0 = ((size_t)r * PADK + k0 + t * 2) * 2;
                size_t o1 = ((size_t)(r + 8) * PADK + k0 + t * 2) * 2;
                ah[mt][0] = *(uint32_t*)(Ahi + o0);
                ah[mt][1] = *(uint32_t*)(Ahi + o1);
                ah[mt][2] = *(uint32_t*)(Ahi + o0 + 16);
                ah[mt][3] = *(uint32_t*)(Ahi + o1 + 16);
                al[mt][0] = *(uint32_t*)(Alo + o0);
                al[mt][1] = *(uint32_t*)(Alo + o1);
                al[mt][2] = *(uint32_t*)(Alo + o0 + 16);
                al[mt][3] = *(uint32_t*)(Alo + o1 + 16);
            }
            #pragma unroll
            for (int nt = 0; nt < 8; nt++) {
                int n = nw * 64 + nt * 8 + g;
                size_t o = ((size_t)n * PADK + k0 + t * 2) * 2;
                bh[nt][0] = *(uint32_t*)(Whi + o);
                bh[nt][1] = *(uint32_t*)(Whi + o + 16);
                bl[nt][0] = *(uint32_t*)(Wlo + o);
                bl[nt][1] = *(uint32_t*)(Wlo + o + 16);
            }
            #pragma unroll
            for (int mt = 0; mt < 2; mt++)
                #pragma unroll
                for (int nt = 0; nt < 8; nt++) {
                    mma16816(acc[mt][nt], ah[mt], bh[nt]);
                    mma16816(acc[mt][nt], al[mt], bh[nt]);
                    mma16816(acc[mt][nt], ah[mt], bl[nt]);
                }
        }
        __syncthreads();   // all warps done with smem before restage / scr
    }

    // ---- epilogue: stores + BN column partials
    #pragma unroll
    for (int nt = 0; nt < 8; nt++) {
        int col = nw * 64 + nt * 8 + t * 2;
        float b0v = sbias[col], b1v = sbias[col + 1];
        float s0 = 0.f, s1 = 0.f, q0 = 0.f, q1 = 0.f;
        #pragma unroll
        for (int mt = 0; mt < 2; mt++) {
            int r = mw * 32 + mt * 16 + g;
            int gm = m0 + r;
            float v00 = acc[mt][nt][0] + b0v;
            float v01 = acc[mt][nt][1] + b1v;
            float v10 = acc[mt][nt][2] + b0v;
            float v11 = acc[mt][nt][3] + b1v;
            if (gm < M) {
                *(float2*)&Zout[(size_t)gm * HID + col] = make_float2(v00, v01);
                s0 += v00; s1 += v01; q0 += v00 * v00; q1 += v01 * v01;
            }
            if (gm + 8 < M) {
                *(float2*)&Zout[(size_t)(gm + 8) * HID + col] = make_float2(v10, v11);
                s0 += v10; s1 += v11; q0 += v10 * v10; q1 += v11 * v11;
            }
        }
        if (part) {
            #pragma unroll
            for (int o = 16; o >= 4; o >>= 1) {   // offsets 16,8,4 keep t fixed
                s0 += __shfl_down_sync(0xffffffffu, s0, o);
                s1 += __shfl_down_sync(0xffffffffu, s1, o);
                q0 += __shfl_down_sync(0xffffffffu, q0, o);
                q1 += __shfl_down_sync(0xffffffffu, q1, o);
            }
            if (lane < 4) {
                int c = nw * 64 + nt * 8 + lane * 2;
                scr[mw * 128 + c] = s0;
                scr[mw * 128 + c + 1] = s1;
                scr[512 + mw * 128 + c] = q0;
                scr[512 + mw * 128 + c + 1] = q1;
            }
        }
    }

    if (part) {
        __syncthreads();
        if (tid < 128) {
            float s = scr[tid] + scr[128 + tid] + scr[256 + tid] + scr[384 + tid];
            float q = scr[512 + tid] + scr[640 + tid] + scr[768 + tid] + scr[896 + tid];
            part[blockIdx.x * 256 + tid] = s;
            part[blockIdx.x * 256 + 128 + tid] = q;
        }
    }
}

// ============================ CSR construction ==============================
__global__ void k_count(const int* __restrict__ dst, int E) {
    int e = blockIdx.x * blockDim.x + threadIdx.x;
    if (e < E) atomicAdd(&g_deg[dst[e]], 1);
}

__global__ void k_scanA(int M) {
    __shared__ int sh[1024];
    int i = blockIdx.x * 1024 + threadIdx.x;
    int v = (i < M) ? g_deg[i] : 0;
    sh[threadIdx.x] = v;
    __syncthreads();
    #pragma unroll
    for (int d = 1; d < 1024; d <<= 1) {
        int tt = (threadIdx.x >= d) ? sh[threadIdx.x - d] : 0;
        __syncthreads();
        sh[threadIdx.x] += tt;
        __syncthreads();
    }
    if (i < M) g_off[i + 1] = sh[threadIdx.x];
    if (threadIdx.x == 1023) g_bsum[blockIdx.x] = sh[1023];
}

__global__ void k_scanB(int nb) {
    int t = threadIdx.x;
    int orig = (t < nb) ? g_bsum[t] : 0;
    int v = orig;
    #pragma unroll
    for (int o = 1; o < 32; o <<= 1) {
        int u = __shfl_up_sync(0xffffffffu, v, o);
        if ((t & 31) >= o) v += u;
    }
    __shared__ int ws[4];
    if ((t & 31) == 31) ws[t >> 5] = v;
    __syncthreads();
    int add = 0;
    #pragma unroll
    for (int w = 0; w < 4; w++) add += (w < (t >> 5)) ? ws[w] : 0;
    v += add;
    if (t < nb) g_bsum[t] = v - orig;
}

__global__ void k_scanC(int M) {
    int i = blockIdx.x * blockDim.x + threadIdx.x;
    if (i < M) {
        int inc = g_off[i + 1] + g_bsum[i >> 10];
        g_off[i + 1] = inc;
        g_cur[i] = inc - g_deg[i];
        if (i == 0) g_off[0] = 0;
    }
}

__global__ void k_scatter(const int* __restrict__ src, const int* __restrict__ dst, int E) {
    int e = blockIdx.x * blockDim.x + threadIdx.x;
    if (e < E) {
        int pos = atomicAdd(&g_cur[dst[e]], 1);
        g_srcs[pos] = src[e];
    }
}

// ============================ max aggregation ===============================
__global__ __launch_bounds__(256) void k_agg(const float* __restrict__ Hin,
                                             const float* __restrict__ stats,
                                             int hasStats, int M)
{
    int n = blockIdx.x * 8 + (threadIdx.x >> 5);
    if (n >= M) return;
    int lane = threadIdx.x & 31;

    float4 sc, sh;
    if (hasStats) {
        sc = *(const float4*)&stats[lane * 4];
        sh = *(const float4*)&stats[128 + lane * 4];
    }

    int s = g_off[n], e = g_off[n + 1];
    float4 m = make_float4(-3.4e38f, -3.4e38f, -3.4e38f, -3.4e38f);
    int j = s;
    for (; j + 4 <= e; j += 4) {
        int s0 = g_srcs[j], s1 = g_srcs[j + 1], s2 = g_srcs[j + 2], s3 = g_srcs[j + 3];
        float4 v0 = *(const float4*)&Hin[(size_t)s0 * HID + lane * 4];
        float4 v1 = *(const float4*)&Hin[(size_t)s1 * HID + lane * 4];
        float4 v2 = *(const float4*)&Hin[(size_t)s2 * HID + lane * 4];
        float4 v3 = *(const float4*)&Hin[(size_t)s3 * HID + lane * 4];
        if (hasStats) {
            v0 = xform4(v0, sc, sh); v1 = xform4(v1, sc, sh);
            v2 = xform4(v2, sc, sh); v3 = xform4(v3, sc, sh);
        }
        m = max4(m, max4(max4(v0, v1), max4(v2, v3)));
    }
    for (; j < e; ++j) {
        float4 v = *(const float4*)&Hin[(size_t)g_srcs[j] * HID + lane * 4];
        if (hasStats) v = xform4(v, sc, sh);
        m = max4(m, v);
    }
    if (e == s) m = make_float4(0.f, 0.f, 0.f, 0.f);
    *(float4*)&g_A[(size_t)n * HID + lane * 4] = m;
}

// ============================ BN stats finalize =============================
__global__ __launch_bounds__(1024) void k_bnfinal(
    const float* __restrict__ g, const float* __restrict__ be,
    float* __restrict__ statsOut, int M, int NB)
{
    __shared__ double sD[8][128];
    __shared__ double qD[8][128];
    int tid = threadIdx.x;
    int grp = tid >> 7;
    int c = tid & 127;
    double s = 0.0, q = 0.0;
    for (int b = grp; b < NB; b += 8) {
        s += (double)g_part[b * 256 + c];
        q += (double)g_part[b * 256 + 128 + c];
    }
    sD[grp][c] = s; qD[grp][c] = q;
    __syncthreads();
    if (tid < 128) {
        double ss = 0.0, qq = 0.0;
        #pragma unroll
        for (int gg = 0; gg < 8; gg++) { ss += sD[gg][tid]; qq += qD[gg][tid]; }
        double mean = ss / (double)M;
        double var = qq / (double)M - mean * mean;
        float rstd = (float)(1.0 / sqrt(var + 1e-5));
        float scale = g[tid] * rstd;
        statsOut[tid] = scale;
        statsOut[128 + tid] = be[tid] - (float)mean * scale;
    }
}

// ============================ head (warp per row) ===========================
__global__ __launch_bounds__(256) void k_fc(
    const float* __restrict__ Zlast, const float* __restrict__ stats,
    const float* __restrict__ W1, const float* __restrict__ b1,
    const float* __restrict__ W2, const float* __restrict__ b2,
    float* __restrict__ out, int M)
{
    __shared__ float W1s[64][132];
    __shared__ float b1s[64], w2s[64];
    __shared__ float xsh[8][128];

    int tid = threadIdx.x;
    int wid = tid >> 5;
    int lane = tid & 31;

    for (int i = tid; i < 64 * 128; i += 256) W1s[i >> 7][i & 127] = W1[i];
    if (tid < 64) { b1s[tid] = b1[tid]; w2s[tid] = W2[tid]; }
    __syncthreads();

    float4 sc = *(const float4*)&stats[lane * 4];
    float4 sh = *(const float4*)&stats[128 + lane * 4];
    float bias2 = b2[0];
    float w2a = w2s[lane], w2b = w2s[lane + 32];
    float b1a = b1s[lane], b1b = b1s[lane + 32];

    const int ROWS = 8;
    int rbase = blockIdx.x * (8 * ROWS) + wid * ROWS;

    for (int rr = 0; rr < ROWS; rr++) {
        int r = rbase + rr;
        if (r >= M) return;
        float4 z = *(const float4*)&Zlast[(size_t)r * HID + lane * 4];
        float4 h = *(const float4*)&g_H0[(size_t)r * HID + lane * 4];
        z = xform4(z, sc, sh);
        z.x += h.x; z.y += h.y; z.z += h.z; z.w += h.w;
        *(float4*)&xsh[wid][lane * 4] = z;
        __syncwarp();

        float acc0 = 0.f, acc1 = 0.f;
        #pragma unroll
        for (int k = 0; k < 128; k += 4) {
            float4 xv = *(const float4*)&xsh[wid][k];
            float4 w0 = *(const float4*)&W1s[lane][k];
            float4 w1 = *(const float4*)&W1s[lane + 32][k];
            acc0 = fmaf(xv.x, w0.x, acc0); acc0 = fmaf(xv.y, w0.y, acc0);
            acc0 = fmaf(xv.z, w0.z, acc0); acc0 = fmaf(xv.w, w0.w, acc0);
            acc1 = fmaf(xv.x, w1.x, acc1); acc1 = fmaf(xv.y, w1.y, acc1);
            acc1 = fmaf(xv.z, w1.z, acc1); acc1 = fmaf(xv.w, w1.w, acc1);
        }
        float f0 = lrelu(acc0 + b1a);
        float f1 = lrelu(acc1 + b1b);
        float contrib = f0 * w2a + f1 * w2b;
        #pragma unroll
        for (int o = 16; o > 0; o >>= 1)
            contrib += __shfl_down_sync(0xffffffffu, contrib, o);
        if (lane == 0) out[r] = contrib + bias2;
        __syncwarp();
    }
}

// ============================ launch ========================================
extern "C" void kernel_launch(void* const* d_in, const int* in_sizes, int n_in,
                              void* d_out, int out_size)
{
    const float* x    = (const float*)d_in[0];
    const int*   ei   = (const int*)d_in[1];
    const float* W_in = (const float*)d_in[2];
    const float* b_in = (const float*)d_in[3];
    const float* Wl[3] = { (const float*)d_in[4], (const float*)d_in[7], (const float*)d_in[10] };
    const float* bl[3] = { (const float*)d_in[5], (const float*)d_in[8], (const float*)d_in[11] };
    const float* Wr[3] = { (const float*)d_in[6], (const float*)d_in[9], (const float*)d_in[12] };
    const float* gm[3] = { (const float*)d_in[13], (const float*)d_in[15], (const float*)d_in[17] };
    const float* be[3] = { (const float*)d_in[14], (const float*)d_in[16], (const float*)d_in[18] };
    const float* W_fc1 = (const float*)d_in[19];
    const float* b_fc1 = (const float*)d_in[20];
    const float* W_fc2 = (const float*)d_in[21];
    const float* b_fc2 = (const float*)d_in[22];
    float* out = (float*)d_out;

    int M = in_sizes[0] / HID;
    int E = in_sizes[1] / 2;
    const int* src = ei;
    const int* dst = ei + E;

    cudaFuncSetAttribute(gemm_mma, cudaFuncAttributeMaxDynamicSharedMemorySize,
                         SM_GEMM_TOTAL);

    void *pH0v, *pAv, *pZv, *pPartv, *pStatsv, *pDegv;
    cudaGetSymbolAddress(&pH0v, g_H0);
    cudaGetSymbolAddress(&pAv, g_A);
    cudaGetSymbolAddress(&pZv, g_Zb);
    cudaGetSymbolAddress(&pPartv, g_part);
    cudaGetSymbolAddress(&pStatsv, g_statsBuf);
    cudaGetSymbolAddress(&pDegv, g_deg);
    float* pH0 = (float*)pH0v;
    float* pA = (float*)pAv;
    float* pZ0 = (float*)pZv;
    float* pZ1 = pZ0 + (size_t)NMAX * HID;
    float* pPart = (float*)pPartv;
    float* pStats0 = (float*)pStatsv;
    float* pStats1 = pStats0 + 256;

    int scanBlocks = (M + 1023) / 1024;
    int gemmGrid = (M + 127) / 128;
    int aggGrid = (M + 7) / 8;

    // ---- CSR build; input-proj GEMM is the 4th launch (ncu target)
    cudaMemsetAsync(pDegv, 0, (size_t)M * sizeof(int));
    k_count<<<(E + 511) / 512, 512>>>(dst, E);                          // 1
    k_scanA<<<scanBlocks, 1024>>>(M);                                   // 2
    k_scanB<<<1, 128>>>(scanBlocks);                                    // 3
    gemm_mma<<<gemmGrid, 256, SM_GEMM_TOTAL>>>(x, nullptr, nullptr,     // 4 (profiled)
                                               W_in, nullptr, b_in,
                                               pH0, nullptr, M, 1, 0);
    k_scanC<<<(M + 255) / 256, 256>>>(M);                               // 5
    k_scatter<<<(E + 511) / 512, 512>>>(src, dst, E);                   // 6

    // ---- layer 1
    k_agg<<<aggGrid, 256>>>(pH0, nullptr, 0, M);
    gemm_mma<<<gemmGrid, 256, SM_GEMM_TOTAL>>>(pA, pH0, nullptr, Wl[0], Wr[0],
                                               bl[0], pZ0, pPart, M, 2, 0);
    k_bnfinal<<<1, 1024>>>(gm[0], be[0], pStats0, M, gemmGrid);

    // ---- layer 2
    k_agg<<<aggGrid, 256>>>(pZ0, pStats0, 1, M);
    gemm_mma<<<gemmGrid, 256, SM_GEMM_TOTAL>>>(pA, pZ0, pStats0, Wl[1], Wr[1],
                                               bl[1], pZ1, pPart, M, 2, 1);
    k_bnfinal<<<1, 1024>>>(gm[1], be[1], pStats1, M, gemmGrid);

    // ---- layer 3
    k_agg<<<aggGrid, 256>>>(pZ1, pStats1, 1, M);
    gemm_mma<<<gemmGrid, 256, SM_GEMM_TOTAL>>>(pA, pZ1, pStats1, Wl[2], Wr[2],
                                               bl[2], pZ0, pPart, M, 2, 1);
    k_bnfinal<<<1, 1024>>>(gm[2], be[2], pStats0, M, gemmGrid);

    // ---- head
    k_fc<<<(M + 63) / 64, 256>>>(pZ0, pStats0, W_fc1, b_fc1, W_fc2, b_fc2, out, M);
}